// round 14
// baseline (speedup 1.0000x reference)
#include <cuda_runtime.h>
#include <cuda_fp16.h>
#include <math.h>
#include <stdint.h>

#define BB   4
#define TT   4096
#define DD   512
#define MM   (BB*TT)        // 16384 tokens
#define DIN  640            // D + DB
#define NCOL 116

// ---------------- scratch ----------------
__device__ float  g_bl[MM];
__device__ float  g_bsoft[MM];
__device__ __half g_filmin[(size_t)MM*DD];     // now hg = h*g_head (K=512)
__device__ __half g_nh[(size_t)MM*DD];
__device__ __half g_z[(size_t)MM*DD];
__device__ __half g_ht[(size_t)MM*DD];
__device__ float4 g_st[MM];                    // (bs, mu, rstd, 0)
__device__ float  g_v[4*1024];                 // v0,v1,v2,v3
__device__ float  g_sh[(size_t)4*MM];
__device__ float  g_sz[(size_t)4*MM];
__device__ __half g_pool[(size_t)4*MM*DD];
__device__ __half g_p1[(size_t)MM*2048];
__device__ __half g_wt_film[(size_t)1024*DD];  // W_head^T, gamma/beta interleaved rows
__device__ __half g_wt_attn[(size_t)1024*DD];
__device__ __half g_wt_proj[(size_t)2048*DD];
__device__ __half g_wc[(size_t)4*128*DD];
__device__ float  g_bc[4*128];

// ---------------- side stream ----------------
struct SideStream {
    cudaStream_t s2;
    cudaEvent_t evF, evP, evH;
    SideStream(){
        cudaStreamCreateWithFlags(&s2, cudaStreamNonBlocking);
        cudaEventCreateWithFlags(&evF, cudaEventDisableTiming);
        cudaEventCreateWithFlags(&evP, cudaEventDisableTiming);
        cudaEventCreateWithFlags(&evH, cudaEventDisableTiming);
    }
};
static SideStream g_ss;

// ================= helpers =================
__device__ __forceinline__ void cp16(uint32_t dst, const void* src){
    asm volatile("cp.async.cg.shared.global [%0], [%1], 16;" :: "r"(dst), "l"(src));
}
__device__ __forceinline__ uint32_t smem_u32(const void* p){
    uint32_t a;
    asm("{ .reg .u64 t; cvta.to.shared.u64 t, %1; cvt.u32.u64 %0, t; }" : "=r"(a) : "l"(p));
    return a;
}
__device__ __forceinline__ float gelu_f(float x){
    return 0.5f*x*(1.0f+erff(x*0.70710678118654752440f));
}
__device__ __forceinline__ float warp_sum(float v){
#pragma unroll
    for(int o=16;o;o>>=1) v += __shfl_xor_sync(0xffffffffu, v, o);
    return v;
}
__device__ __forceinline__ void mma_f16(float* c, const uint32_t* a, const uint32_t* b){
    asm volatile(
        "mma.sync.aligned.m16n8k16.row.col.f32.f16.f16.f32 "
        "{%0,%1,%2,%3}, {%4,%5,%6,%7}, {%8,%9}, {%0,%1,%2,%3};"
        : "+f"(c[0]), "+f"(c[1]), "+f"(c[2]), "+f"(c[3])
        : "r"(a[0]), "r"(a[1]), "r"(a[2]), "r"(a[3]), "r"(b[0]), "r"(b[1]));
}
__device__ __forceinline__ void ldsm4(uint32_t* r, uint32_t addr){
    asm volatile("ldmatrix.sync.aligned.m8n8.x4.shared.b16 {%0,%1,%2,%3}, [%4];"
        : "=r"(r[0]), "=r"(r[1]), "=r"(r[2]), "=r"(r[3]) : "r"(addr));
}

// ================= FP16 mma.sync GEMM, 128x128 tile, BK=64, XOR swizzle, 3 stages, occ=2 =================
// act: 0=f32, 1=gelu->half (p1 layout), 2=attn score (atomicAdd),
//      3=FiLM z->half (K=512 algebra: bias=stats float4, w2=nh half, b2=g_v),
//      4=per-head vocab out
#define STG_A 16384
#define STG_BYTES 32768
#define TG_SMEM (3*STG_BYTES)      // 98304 -> 2 CTAs/SM

__device__ __forceinline__ void tg_load(uint32_t sA, uint32_t sB,
                                        const __half* Ap, int lda,
                                        const __half* Bp, int ldb, int tid){
#pragma unroll
    for(int i=0;i<4;i++){
        int idx = tid + i*256;
        int row = idx>>3, cw = idx&7;
        uint32_t off = row*128 + ((cw ^ (row&7))*16);
        cp16(sA + off, Ap + (size_t)row*lda + cw*8);
    }
#pragma unroll
    for(int i=0;i<4;i++){
        int idx = tid + i*256;
        int row = idx>>3, cw = idx&7;
        uint32_t off = row*128 + ((cw ^ (row&7))*16);
        cp16(sB + off, Bp + (size_t)row*ldb + cw*8);
    }
    asm volatile("cp.async.commit_group;" ::: "memory");
}

__global__ void __launch_bounds__(256, 2) tgemm(
    int K, const __half* __restrict__ A, int lda,
    const __half* __restrict__ Bt, int ldb,
    float* __restrict__ C, int ldc,
    const float* __restrict__ bias, int act,
    const float* __restrict__ w2, const float* __restrict__ b2,
    long long strideA, long long strideB, long long strideC, int strideBias)
{
    extern __shared__ char smemc[];
    float* smem = (float*)smemc;
    const int tid  = threadIdx.x;
    const int wid  = tid>>5, lane = tid&31;
    const int bm   = blockIdx.y*128;
    const int bn   = blockIdx.x*128;
    const int zb   = blockIdx.z;
    A  += (size_t)zb*strideA;
    Bt += (size_t)zb*strideB;
    if(bias) bias += (size_t)zb*strideBias;

    const int wm0 = (wid>>2)*64;
    const int wn0 = (wid&3)*32;
    const int gid = lane>>2;
    const int tig = lane&3;

    uint32_t sbase = smem_u32(smemc);
    const __half* Abase = A + (size_t)bm*lda;
    const __half* Bbase = Bt + (size_t)bn*ldb;
    const int KL = K >> 6;     // BK=64

    float acc[4][4][4];
#pragma unroll
    for(int i=0;i<4;i++)
#pragma unroll
        for(int j=0;j<4;j++)
#pragma unroll
            for(int q=0;q<4;q++) acc[i][j][q]=0.f;

    tg_load(sbase,              sbase + STG_A,              Abase,    lda, Bbase,    ldb, tid);
    tg_load(sbase + STG_BYTES,  sbase + STG_BYTES + STG_A,  Abase+64, lda, Bbase+64, ldb, tid);

    // hoisted per-thread fragment offsets (within a stage)
    const int rA  = wm0 + (lane&15);
    const int cA0 = lane>>4;
    const int xA  = rA & 7;
    const int rB  = wn0 + (lane&7) + ((lane>>4)&1)*8;
    const int cB0 = (lane>>3)&1;
    const int xB  = rB & 7;
    uint32_t offA[4], offB[4];
#pragma unroll
    for(int kst=0; kst<4; kst++){
        offA[kst] = (uint32_t)rA*128 + (uint32_t)(((cA0 + kst*2) ^ xA)*16);
        offB[kst] = (uint32_t)rB*128 + (uint32_t)(((cB0 + kst*2) ^ xB)*16);
    }
    // spread-prefetch addressing (constant across chunks)
    const int pr0 = tid>>3, pcw = tid&7;
    const uint32_t poff0 = (uint32_t)pr0*128 + (uint32_t)((pcw ^ (pr0&7))*16);

    for(int kc=0; kc<KL; kc++){
        if(kc+1<KL) asm volatile("cp.async.wait_group 1;" ::: "memory");
        else        asm volatile("cp.async.wait_group 0;" ::: "memory");
        __syncthreads();
        const int do_pf = (kc+2 < KL);
        uint32_t pfA = 0, pfB = 0;
        const __half *pA = nullptr, *pB = nullptr;
        if(do_pf){
            int ns = kc+2; ns -= (ns/3)*3;
            pfA = sbase + ns*STG_BYTES;
            pfB = pfA + STG_A;
            pA = Abase + (kc+2)*64 + (size_t)pr0*lda + pcw*8;
            pB = Bbase + (kc+2)*64 + (size_t)pr0*ldb + pcw*8;
        }
        int s = kc - (kc/3)*3;
        uint32_t sA = sbase + s*STG_BYTES;
        uint32_t sB = sA + STG_A;
#pragma unroll
        for(int kst=0; kst<4; kst++){
            if(do_pf){
                cp16(pfA + poff0 + kst*4096, pA + (size_t)kst*32*lda);
                cp16(pfB + poff0 + kst*4096, pB + (size_t)kst*32*ldb);
                if(kst==3) asm volatile("cp.async.commit_group;" ::: "memory");
            }
            uint32_t aT = sA + offA[kst];
            uint32_t bT = sB + offB[kst];
            uint32_t af[4][4], bf[4][2];
#pragma unroll
            for(int mt=0; mt<4; mt++)
                ldsm4(af[mt], aT + mt*16*128);
#pragma unroll
            for(int p=0; p<2; p++){
                uint32_t t4[4];
                ldsm4(t4, bT + p*16*128);
                bf[2*p][0]=t4[0];   bf[2*p][1]=t4[1];
                bf[2*p+1][0]=t4[2]; bf[2*p+1][1]=t4[3];
            }
#pragma unroll
            for(int mt=0; mt<4; mt++)
#pragma unroll
                for(int nt=0; nt<4; nt++)
                    mma_f16(acc[mt][nt], af[mt], bf[nt]);
        }
    }
    __syncthreads();

    if(act==2){
        // fused attn score partial (128 cols); head = blockIdx.x>>1; C pre-init w/ b2
        float rsum[4][2];
#pragma unroll
        for(int mt=0;mt<4;mt++){ rsum[mt][0]=0.f; rsum[mt][1]=0.f; }
#pragma unroll
        for(int nt=0; nt<4; nt++){
            int gcol = bn + wn0 + nt*8 + tig*2;
            float b0v = bias[gcol], b1v = bias[gcol+1];
            float w0  = w2[gcol],  w1  = w2[gcol+1];
#pragma unroll
            for(int mt=0; mt<4; mt++){
                rsum[mt][0] += gelu_f(acc[mt][nt][0]+b0v)*w0 + gelu_f(acc[mt][nt][1]+b1v)*w1;
                rsum[mt][1] += gelu_f(acc[mt][nt][2]+b0v)*w0 + gelu_f(acc[mt][nt][3]+b1v)*w1;
            }
        }
#pragma unroll
        for(int mt=0; mt<4; mt++)
#pragma unroll
            for(int hh=0; hh<2; hh++){
                rsum[mt][hh] += __shfl_xor_sync(0xffffffffu, rsum[mt][hh], 1);
                rsum[mt][hh] += __shfl_xor_sync(0xffffffffu, rsum[mt][hh], 2);
            }
        float* red = smem;
        if(tig==0){
#pragma unroll
            for(int mt=0; mt<4; mt++)
#pragma unroll
                for(int hh=0; hh<2; hh++)
                    red[(wid&3)*128 + wm0 + mt*16 + hh*8 + gid] = rsum[mt][hh];
        }
        __syncthreads();
        if(tid < 128){
            float sv = red[tid] + red[128+tid] + red[256+tid] + red[384+tid];
            atomicAdd(&C[(size_t)(blockIdx.x>>1)*MM + bm + tid], sv);
        }
        return;
    }

    if(act==3){
        // FiLM with K=512 algebra:
        // gamma = rstd*(acc_g + v0g + bs*v1g - mu*v2g) + v3g; same for beta with +512 cols
        const __half* nh = (const __half*)w2;
        const float4* st = (const float4*)bias;
        const float* v = b2;     // [4][1024]
        __half* Ch = (__half*)C;
#pragma unroll
        for(int mt=0; mt<4; mt++){
            int r0 = bm + wm0 + mt*16 + gid;
            float4 s0 = st[r0];
            float4 s1 = st[r0+8];
#pragma unroll
            for(int nt=0; nt<4; nt++){
                int c0 = bn + wn0 + nt*8 + tig*2;
                int j  = c0 >> 1;
                float v0g=v[j],      v1g=v[1024+j], v2g=v[2048+j], v3g=v[3072+j];
                float v0b=v[512+j],  v1b=v[1536+j], v2b=v[2560+j], v3b=v[3584+j];
                float gam0 = s0.z*(acc[mt][nt][0] + v0g + s0.x*v1g - s0.y*v2g) + v3g;
                float bet0 = s0.z*(acc[mt][nt][1] + v0b + s0.x*v1b - s0.y*v2b) + v3b;
                float gam1 = s1.z*(acc[mt][nt][2] + v0g + s1.x*v1g - s1.y*v2g) + v3g;
                float bet1 = s1.z*(acc[mt][nt][3] + v0b + s1.x*v1b - s1.y*v2b) + v3b;
                float nh0 = __half2float(nh[(size_t)r0*DD + j]);
                float nh1 = __half2float(nh[(size_t)(r0+8)*DD + j]);
                Ch[(size_t)r0*ldc + j]     = __float2half_rn(fmaf(nh0, 1.f+gam0, bet0));
                Ch[(size_t)(r0+8)*ldc + j] = __float2half_rn(fmaf(nh1, 1.f+gam1, bet1));
            }
        }
        return;
    }

    if(act==1){
        __half* Ch = (__half*)C + (size_t)zb*strideC;
#pragma unroll
        for(int mt=0; mt<4; mt++){
            int r0 = bm + wm0 + mt*16 + gid;
#pragma unroll
            for(int nt=0; nt<4; nt++){
                int col = bn + wn0 + nt*8 + tig*2;
                float b0v = bias[col], b1v = bias[col+1];
                __half2 o0 = __floats2half2_rn(gelu_f(acc[mt][nt][0]+b0v),
                                               gelu_f(acc[mt][nt][1]+b1v));
                __half2 o1 = __floats2half2_rn(gelu_f(acc[mt][nt][2]+b0v),
                                               gelu_f(acc[mt][nt][3]+b1v));
                *(__half2*)(Ch + (size_t)r0*ldc + col)     = o0;
                *(__half2*)(Ch + (size_t)(r0+8)*ldc + col) = o1;
            }
        }
        return;
    }

    if(act==4){
        int vocab = (zb==0) ? 64 : (zb==3) ? 25 : 13;
        int off   = (zb==0) ? 0 : (zb==1) ? 64 : (zb==2) ? 77 : 90;
#pragma unroll
        for(int mt=0; mt<4; mt++){
            int r0 = bm + wm0 + mt*16 + gid;
#pragma unroll
            for(int nt=0; nt<4; nt++){
                int col = wn0 + nt*8 + tig*2;
                if(col < vocab){
                    C[(size_t)r0*ldc + off + col]     = acc[mt][nt][0] + bias[col];
                    C[(size_t)(r0+8)*ldc + off + col] = acc[mt][nt][2] + bias[col];
                }
                if(col+1 < vocab){
                    C[(size_t)r0*ldc + off + col+1]     = acc[mt][nt][1] + bias[col+1];
                    C[(size_t)(r0+8)*ldc + off + col+1] = acc[mt][nt][3] + bias[col+1];
                }
            }
        }
        return;
    }

    C += (size_t)zb*strideC;
#pragma unroll
    for(int mt=0; mt<4; mt++){
        int r0 = bm + wm0 + mt*16 + gid;
#pragma unroll
        for(int nt=0; nt<4; nt++){
            int col = bn + wn0 + nt*8 + tig*2;
            float2 v0 = make_float2(acc[mt][nt][0], acc[mt][nt][1]);
            float2 v1 = make_float2(acc[mt][nt][2], acc[mt][nt][3]);
            if(bias){
                float b0v = bias[col], b1v = bias[col+1];
                v0.x += b0v; v0.y += b1v; v1.x += b0v; v1.y += b1v;
            }
            *(float2*)(C + (size_t)r0*ldc + col)     = v0;
            *(float2*)(C + (size_t)(r0+8)*ldc + col) = v1;
        }
    }
}

// init score array: dst[k*MM + t] = b2[k]
__global__ void k_sinit(float* __restrict__ dst, const float* __restrict__ b2){
    int i = blockIdx.x*256 + threadIdx.x;
    dst[i] = b2[i >> 14];
}

// GEMV: v0..v3 vectors for film algebra
__global__ void k_gemv(const float* __restrict__ film_w,
                       const float* __restrict__ e0, const float* __restrict__ e1,
                       const float* __restrict__ g,  const float* __restrict__ bb,
                       const float* __restrict__ film_b){
    int j = blockIdx.x*128 + threadIdx.x;
    float a0=0.f, a1=0.f, a2=0.f, a3=0.f;
    for(int i=0;i<DIN;i++){
        float w = film_w[(size_t)i*1024 + j];
        float gi = g[i];
        if(i>=DD){
            float ev = e0[i-DD];
            a0 += ev*gi*w;
            a1 += (e1[i-DD]-ev)*gi*w;
        }
        a2 += gi*w;
        a3 += bb[i]*w;
    }
    g_v[j]        = a0;
    g_v[1024 + j] = a1;
    g_v[2048 + j] = a2;
    g_v[3072 + j] = a3 + film_b[j];
}

// ================= fused prep =================
__device__ __forceinline__ void do_transpose(const float* __restrict__ src,
                                             __half* __restrict__ dst,
                                             int R, int C, int bx, int by,
                                             float tile[32][33]){
    int c0 = bx*32, r0 = by*32;
    int tx = threadIdx.x, ty = threadIdx.y;
#pragma unroll
    for(int i=0;i<32;i+=8)
        tile[ty+i][tx] = src[(size_t)(r0+ty+i)*C + c0+tx];
    __syncthreads();
#pragma unroll
    for(int i=0;i<32;i+=8)
        dst[(size_t)(c0+ty+i)*R + r0+tx] = __float2half_rn(tile[tx][ty+i]);
}

// blocks: [0,512) film-head; [512,1024) attn; [1024,2048) proj; [2048,10240) h; [10240,10752) wc
__global__ void k_prep(const float* __restrict__ film_w,
                       const float* __restrict__ attn_w1,
                       const float* __restrict__ proj_w1,
                       const float* __restrict__ h,
                       const float* __restrict__ w2q, const float* __restrict__ b2q,
                       const float* __restrict__ w2r, const float* __restrict__ b2r,
                       const float* __restrict__ w2b, const float* __restrict__ b2b,
                       const float* __restrict__ w2k, const float* __restrict__ b2k){
    __shared__ float tile[32][33];
    int b = blockIdx.x;
    if(b < 512){
        // film W_head: rows [0,512) of film_w, interleaved gamma/beta dst rows, K=512
        int bx = b&31, by = b>>5;      // 32 col-blocks, 16 row-blocks
        int c0 = bx*32, r0 = by*32;
        int tx = threadIdx.x, ty = threadIdx.y;
#pragma unroll
        for(int i=0;i<32;i+=8)
            tile[ty+i][tx] = film_w[(size_t)(r0+ty+i)*1024 + c0+tx];
        __syncthreads();
#pragma unroll
        for(int i=0;i<32;i+=8){
            int c = c0+ty+i;
            int ic = (c<512) ? 2*c : 2*(c-512)+1;
            g_wt_film[(size_t)ic*DD + r0+tx] = __float2half_rn(tile[tx][ty+i]);
        }
    } else if(b < 1024){
        int bb = b - 512;
        int k  = bb >> 7; bb &= 127;
        do_transpose(attn_w1 + (size_t)k*DD*256, g_wt_attn + (size_t)k*256*DD,
                     DD, 256, bb&7, bb>>3, tile);
    } else if(b < 2048){
        int bb = b - 1024;
        int k  = bb >> 8; bb &= 255;
        do_transpose(proj_w1 + (size_t)k*DD*DD, g_wt_proj + (size_t)k*DD*DD,
                     DD, 512, bb&15, bb>>4, tile);
    } else if(b < 10240){
        int bb = b - 2048;
        int tid = threadIdx.y*32 + threadIdx.x;
        size_t i = (size_t)bb*1024 + tid*4;
        float4 v = *(const float4*)(h + i);
        __half2 h0 = __floats2half2_rn(v.x, v.y);
        __half2 h1 = __floats2half2_rn(v.z, v.w);
        *(__half2*)(g_ht + i)     = h0;
        *(__half2*)(g_ht + i + 2) = h1;
    } else {
        int c = b - 10240;
        int k = c >> 7, r = c & 127;
        int tid = threadIdx.y*32 + threadIdx.x;
        int vocab; const float *W, *bs2;
        if(k==0)      { vocab=64; W=w2q; bs2=b2q; }
        else if(k==1) { vocab=13; W=w2r; bs2=b2r; }
        else if(k==2) { vocab=13; W=w2b; bs2=b2b; }
        else          { vocab=25; W=w2k; bs2=b2k; }
        for(int d=tid; d<DD; d+=256){
            float val = (r < vocab) ? W[(size_t)d*vocab + r] : 0.f;
            g_wc[((size_t)k*128 + r)*DD + d] = __float2half_rn(val);
        }
        if(tid == 0) g_bc[k*128 + r] = (r < vocab) ? bs2[r] : 0.f;
    }
}

// ================= stage 1: bl = h . w_bnd + b =================
__global__ void k_bl(const float* __restrict__ h, const float* __restrict__ w,
                     const float* __restrict__ b0, float* __restrict__ out){
    int t    = blockIdx.x*8 + (threadIdx.x>>5);
    int lane = threadIdx.x&31;
    const float4* hr = (const float4*)(h + (size_t)t*DD);
    const float4* w4 = (const float4*)w;
    float acc = 0.f;
#pragma unroll
    for(int i=0;i<4;i++){
        float4 a = hr[lane + i*32];
        float4 b = w4[lane + i*32];
        acc += a.x*b.x + a.y*b.y + a.z*b.z + a.w*b.w;
    }
    acc = warp_sum(acc);
    if(lane==0){
        float v = acc + b0[0];
        g_bl[t] = v;
        out[(size_t)t*NCOL + 115] = v;
    }
}

// ================= stage 2: conv + sigmoid =================
__global__ void k_bsoft(const float* __restrict__ ck, const float* __restrict__ cb){
    int t  = blockIdx.x*256 + threadIdx.x;
    int b  = t / TT, tt = t - b*TT;
    float acc = cb[0];
#pragma unroll
    for(int j=0;j<9;j++){
        int tj = tt + j - 4;
        if(tj>=0 && tj<TT) acc = fmaf(g_bl[b*TT+tj], ck[j], acc);
    }
    g_bsoft[t] = 1.f/(1.f + expf(-acc));
}

// ================= stage 3: stats + hg + nh (+ sz init) =================
__global__ void k_filmin(const float* __restrict__ h, const float* __restrict__ e0,
                         const float* __restrict__ e1, const float* __restrict__ g,
                         const float* __restrict__ lng, const float* __restrict__ lnb,
                         const float* __restrict__ b2a){
    __shared__ float rbuf[4][8];
    int t = blockIdx.x;
    int lane = threadIdx.x&31, wid = threadIdx.x>>5;
    float bs = g_bsoft[t];
    const float* hr = h + (size_t)t*DD;
    float v[3];
#pragma unroll
    for(int c=0;c<3;c++){
        int i = threadIdx.x + c*256;
        float val = 0.f;
        if(i < DIN) val = (i < DD) ? hr[i] : (bs*e1[i-DD] + (1.f-bs)*e0[i-DD]);
        v[c] = val;
    }
    float s4[4];
    s4[0] = v[0]+v[1]+v[2];
    s4[1] = v[0]*v[0]+v[1]*v[1]+v[2]*v[2];
    s4[2] = v[0]+v[1];
    s4[3] = v[0]*v[0]+v[1]*v[1];
#pragma unroll
    for(int q=0;q<4;q++){
        s4[q] = warp_sum(s4[q]);
        if(lane==0) rbuf[q][wid] = s4[q];
    }
    __syncthreads();
    if(wid==0){
#pragma unroll
        for(int q=0;q<4;q++){
            float s = (lane<8)? rbuf[q][lane] : 0.f;
            s = warp_sum(s);
            if(lane==0) rbuf[q][0] = s;
        }
    }
    __syncthreads();
    float mu  = rbuf[0][0] / (float)DIN;
    float var = rbuf[1][0] / (float)DIN - mu*mu;
    float rstd = rsqrtf(var + 1e-5f);
    float muh  = rbuf[2][0] / (float)DD;
    float varh = rbuf[3][0] / (float)DD - muh*muh;
    float rstdh = rsqrtf(varh + 1e-5f);
    if(threadIdx.x == 0) g_st[t] = make_float4(bs, mu, rstd, 0.f);
    if(threadIdx.x < 4)  g_sz[(size_t)threadIdx.x*MM + t] = b2a[threadIdx.x];
#pragma unroll
    for(int c=0;c<2;c++){
        int i = threadIdx.x + c*256;
        g_filmin[(size_t)t*DD + i] = __float2half_rn(v[c]*g[i]);           // hg
        g_nh[(size_t)t*DD + i]     = __float2half_rn((v[c]-muh)*rstdh*lng[i] + lnb[i]);
    }
}

// ================= stage 8: softmax + pool =================
__global__ void k_pool(){
    __shared__ float sa[4][10];
    __shared__ int   sidx[9];
    int t = blockIdx.x;
    int b = t/TT, tt = t - b*TT;
    int tid = threadIdx.x;
    if(tid < 9){
        int tj = tt + tid - 4;
        tj = min(max(tj, 0), TT-1);
        sidx[tid] = b*TT + tj;
    }
    __syncthreads();
    if(tid < 4){
        int k = tid;
        float sc[10];
        sc[0] = g_sz[(size_t)k*MM + t];
#pragma unroll
        for(int j=0;j<9;j++) sc[1+j] = g_sh[(size_t)k*MM + sidx[j]];
        float mx = sc[0];
#pragma unroll
        for(int c=1;c<10;c++) mx = fmaxf(mx, sc[c]);
        float sum = 0.f;
#pragma unroll
        for(int c=0;c<10;c++){ sc[c] = expf(sc[c]-mx); sum += sc[c]; }
        float inv = 1.f/sum;
#pragma unroll
        for(int c=0;c<10;c++) sa[k][c] = sc[c]*inv;
    }
    __syncthreads();
    int d = tid*4;
    const __half2* zp = (const __half2*)(g_z + (size_t)t*DD + d);
    float2 zlo = __half22float2(zp[0]);
    float2 zhi = __half22float2(zp[1]);
    float4 zv = make_float4(zlo.x, zlo.y, zhi.x, zhi.y);
    float4 hv[9];
#pragma unroll
    for(int j=0;j<9;j++){
        const __half2* hp = (const __half2*)(g_ht + (size_t)sidx[j]*DD + d);
        float2 lo = __half22float2(hp[0]);
        float2 hi = __half22float2(hp[1]);
        hv[j] = make_float4(lo.x, lo.y, hi.x, hi.y);
    }
#pragma unroll
    for(int k=0;k<4;k++){
        float4 p;
        p.x = sa[k][0]*zv.x; p.y = sa[k][0]*zv.y;
        p.z = sa[k][0]*zv.z; p.w = sa[k][0]*zv.w;
#pragma unroll
        for(int j=0;j<9;j++){
            float w = sa[k][1+j];
            p.x = fmaf(w, hv[j].x, p.x); p.y = fmaf(w, hv[j].y, p.y);
            p.z = fmaf(w, hv[j].z, p.z); p.w = fmaf(w, hv[j].w, p.w);
        }
        __half2 o0 = __floats2half2_rn(p.x, p.y);
        __half2 o1 = __floats2half2_rn(p.z, p.w);
        __half2* op = (__half2*)(g_pool + ((size_t)k*MM + t)*DD + d);
        op[0] = o0; op[1] = o1;
    }
}

// ================= launch =================
extern "C" void kernel_launch(void* const* d_in, const int* in_sizes, int n_in,
                              void* d_out, int out_size){
    const float* h       = (const float*)d_in[0];
    const float* w_bnd   = (const float*)d_in[1];
    const float* b_bnd   = (const float*)d_in[2];
    const float* conv_k  = (const float*)d_in[3];
    const float* conv_b  = (const float*)d_in[4];
    const float* e0      = (const float*)d_in[5];
    const float* e1      = (const float*)d_in[6];
    const float* ln_in_g = (const float*)d_in[7];
    const float* ln_in_b = (const float*)d_in[8];
    const float* ln_h_g  = (const float*)d_in[9];
    const float* ln_h_b  = (const float*)d_in[10];
    const float* film_w  = (const float*)d_in[11];
    const float* film_b  = (const float*)d_in[12];
    const float* attn_w1 = (const float*)d_in[13];
    const float* attn_b1 = (const float*)d_in[14];
    const float* attn_w2 = (const float*)d_in[15];
    const float* attn_b2 = (const float*)d_in[16];
    const float* proj_w1 = (const float*)d_in[17];
    const float* proj_b1 = (const float*)d_in[18];
    const float* w2q = (const float*)d_in[19]; const float* b2q = (const float*)d_in[20];
    const float* w2r = (const float*)d_in[21]; const float* b2r = (const float*)d_in[22];
    const float* w2b = (const float*)d_in[23]; const float* b2b = (const float*)d_in[24];
    const float* w2k = (const float*)d_in[25]; const float* b2k = (const float*)d_in[26];
    float* out = (float*)d_out;

    __half *p_filmin, *p_nh, *p_z, *p_ht, *p_pool, *p_p1, *p_wtf, *p_wta, *p_wtp, *p_wc;
    float  *p_sh, *p_sz, *p_bc, *p_v, *p_st;
    cudaGetSymbolAddress((void**)&p_filmin, g_filmin);
    cudaGetSymbolAddress((void**)&p_nh,     g_nh);
    cudaGetSymbolAddress((void**)&p_z,      g_z);
    cudaGetSymbolAddress((void**)&p_ht,     g_ht);
    cudaGetSymbolAddress((void**)&p_sh,     g_sh);
    cudaGetSymbolAddress((void**)&p_sz,     g_sz);
    cudaGetSymbolAddress((void**)&p_pool,   g_pool);
    cudaGetSymbolAddress((void**)&p_p1,     g_p1);
    cudaGetSymbolAddress((void**)&p_wtf,    g_wt_film);
    cudaGetSymbolAddress((void**)&p_wta,    g_wt_attn);
    cudaGetSymbolAddress((void**)&p_wtp,    g_wt_proj);
    cudaGetSymbolAddress((void**)&p_wc,     g_wc);
    cudaGetSymbolAddress((void**)&p_bc,     g_bc);
    cudaGetSymbolAddress((void**)&p_v,      g_v);
    cudaGetSymbolAddress((void**)&p_st,     g_st);

    cudaFuncSetAttribute(tgemm, cudaFuncAttributeMaxDynamicSharedMemorySize, TG_SMEM);

    cudaStream_t s2 = g_ss.s2;

    // ---- fork side stream ----
    cudaEventRecord(g_ss.evF, 0);
    cudaStreamWaitEvent(s2, g_ss.evF, 0);

    // [1] prep (s2)
    k_prep<<<10752, dim3(32,8), 0, s2>>>(film_w, attn_w1, proj_w1, h,
                                         w2q, b2q, w2r, b2r, w2b, b2b, w2k, b2k);
    // [2] gemv + init g_sh (s2)
    k_gemv<<<8, 128, 0, s2>>>(film_w, e0, e1, ln_in_g, ln_in_b, film_b);
    k_sinit<<<4*MM/256, 256, 0, s2>>>(p_sh, attn_b2);
    cudaEventRecord(g_ss.evP, s2);
    // [3] bl (main)
    k_bl<<<MM/8, 256>>>(h, w_bnd, b_bnd, out);
    // [4] hW1 + fused score (s2)  <-- profiled launch
    tgemm<<<dim3(1024/128, MM/128, 1), 256, TG_SMEM, s2>>>(
        DD, p_ht, DD, p_wta, DD, p_sh, MM, attn_b1, 2,
        attn_w2, attn_b2, 0,0,0,0);
    cudaEventRecord(g_ss.evH, s2);
    // [5] bsoft (main)
    k_bsoft<<<MM/256, 256>>>(conv_k, conv_b);
    // [6] filmin (main): stats + hg + nh + sz init
    k_filmin<<<MM, 256>>>(h, e0, e1, ln_in_g, ln_h_g, ln_h_b, attn_b2);

    // [7] film GEMM (K=512) + fused z (needs prep + gemv)
    cudaStreamWaitEvent(0, g_ss.evP, 0);
    tgemm<<<dim3(1024/128, MM/128, 1), 256, TG_SMEM>>>(
        DD, p_filmin, DD, p_wtf, DD, (float*)p_z, DD, p_st, 3,
        (const float*)p_nh, p_v, 0,0,0,0);
    // [8] zW1 + fused score
    tgemm<<<dim3(1024/128, MM/128, 1), 256, TG_SMEM>>>(
        DD, p_z, DD, p_wta, DD, p_sz, MM, attn_b1, 2,
        attn_w2, attn_b2, 0,0,0,0);

    // join: pool needs g_sh
    cudaStreamWaitEvent(0, g_ss.evH, 0);
    // [9] pool
    k_pool<<<MM, 128>>>();
    // [10] proj (4 heads via blockIdx.z), half output in [MM,2048] layout
    tgemm<<<dim3(512/128, MM/128, 4), 256, TG_SMEM>>>(
        DD, p_pool, DD, p_wtp, DD, (float*)p_p1, 2048, proj_b1, 1,
        nullptr, nullptr,
        (long long)MM*DD, (long long)DD*DD, 512LL, DD);
    // [11] vocab heads: 4 z-batched per-head GEMMs [MM,512]x[512,128]
    tgemm<<<dim3(1, MM/128, 4), 256, TG_SMEM>>>(
        DD, p_p1, 2048, p_wc, DD, out, NCOL, p_bc, 4,
        nullptr, nullptr, 512LL, (long long)128*DD, 0, 128);
}

// round 15
// speedup vs baseline: 1.4990x; 1.4990x over previous
#include <cuda_runtime.h>
#include <cuda_fp16.h>
#include <math.h>
#include <stdint.h>

#define BB   4
#define TT   4096
#define DD   512
#define MM   (BB*TT)        // 16384 tokens
#define DIN  640            // D + DB
#define NCOL 116

// ---------------- scratch ----------------
__device__ float  g_bl[MM];
__device__ float  g_bsoft[MM];
__device__ __half g_filmin[(size_t)MM*DD];     // hg = h*g_head (K=512)
__device__ __half g_nh[(size_t)MM*DD];
__device__ __half g_z[(size_t)MM*DD];
__device__ __half g_ht[(size_t)MM*DD];
__device__ float4 g_st[MM];                    // (bs, mu, rstd, 0)
__device__ float  g_v[4*1024];                 // v0,v1,v2,v3
__device__ float  g_sh[(size_t)4*MM];
__device__ float  g_sz[(size_t)4*MM];
__device__ __half g_pool[(size_t)4*MM*DD];
__device__ __half g_p1[(size_t)MM*2048];
__device__ __half g_wt_film[(size_t)1024*DD];  // W_head^T, gamma/beta interleaved rows
__device__ __half g_wt_attn[(size_t)1024*DD];
__device__ __half g_wt_proj[(size_t)2048*DD];
__device__ __half g_wc[(size_t)4*128*DD];
__device__ float  g_bc[4*128];

// ---------------- side stream ----------------
struct SideStream {
    cudaStream_t s2;
    cudaEvent_t evF, evP, evH;
    SideStream(){
        cudaStreamCreateWithFlags(&s2, cudaStreamNonBlocking);
        cudaEventCreateWithFlags(&evF, cudaEventDisableTiming);
        cudaEventCreateWithFlags(&evP, cudaEventDisableTiming);
        cudaEventCreateWithFlags(&evH, cudaEventDisableTiming);
    }
};
static SideStream g_ss;

// ================= helpers =================
__device__ __forceinline__ void cp16(uint32_t dst, const void* src){
    asm volatile("cp.async.cg.shared.global [%0], [%1], 16;" :: "r"(dst), "l"(src));
}
__device__ __forceinline__ uint32_t smem_u32(const void* p){
    uint32_t a;
    asm("{ .reg .u64 t; cvta.to.shared.u64 t, %1; cvt.u32.u64 %0, t; }" : "=r"(a) : "l"(p));
    return a;
}
__device__ __forceinline__ float gelu_f(float x){
    return 0.5f*x*(1.0f+erff(x*0.70710678118654752440f));
}
__device__ __forceinline__ float warp_sum(float v){
#pragma unroll
    for(int o=16;o;o>>=1) v += __shfl_xor_sync(0xffffffffu, v, o);
    return v;
}
__device__ __forceinline__ void mma_f16(float* c, const uint32_t* a, const uint32_t* b){
    asm volatile(
        "mma.sync.aligned.m16n8k16.row.col.f32.f16.f16.f32 "
        "{%0,%1,%2,%3}, {%4,%5,%6,%7}, {%8,%9}, {%0,%1,%2,%3};"
        : "+f"(c[0]), "+f"(c[1]), "+f"(c[2]), "+f"(c[3])
        : "r"(a[0]), "r"(a[1]), "r"(a[2]), "r"(a[3]), "r"(b[0]), "r"(b[1]));
}
__device__ __forceinline__ void ldsm4(uint32_t* r, uint32_t addr){
    asm volatile("ldmatrix.sync.aligned.m8n8.x4.shared.b16 {%0,%1,%2,%3}, [%4];"
        : "=r"(r[0]), "=r"(r[1]), "=r"(r[2]), "=r"(r[3]) : "r"(addr));
}

// ================= FP16 mma.sync GEMM, 128x128 tile, BK=64, XOR swizzle, 3 stages, occ=2 =================
// (R13 structure: burst prefetch, hoisted fragment offsets)
// act: 0=f32, 1=gelu->half (p1 layout), 2=attn score (atomicAdd),
//      3=FiLM z->half (K=512 algebra: bias=stats float4, w2=nh half, b2=g_v),
//      4=per-head vocab out
#define STG_A 16384
#define STG_BYTES 32768
#define TG_SMEM (3*STG_BYTES)      // 98304 -> 2 CTAs/SM

__device__ __forceinline__ void tg_load(uint32_t sA, uint32_t sB,
                                        const __half* Ap, int lda,
                                        const __half* Bp, int ldb, int tid){
#pragma unroll
    for(int i=0;i<4;i++){
        int idx = tid + i*256;
        int row = idx>>3, cw = idx&7;
        uint32_t off = row*128 + ((cw ^ (row&7))*16);
        cp16(sA + off, Ap + (size_t)row*lda + cw*8);
    }
#pragma unroll
    for(int i=0;i<4;i++){
        int idx = tid + i*256;
        int row = idx>>3, cw = idx&7;
        uint32_t off = row*128 + ((cw ^ (row&7))*16);
        cp16(sB + off, Bp + (size_t)row*ldb + cw*8);
    }
    asm volatile("cp.async.commit_group;" ::: "memory");
}

__global__ void __launch_bounds__(256, 2) tgemm(
    int K, const __half* __restrict__ A, int lda,
    const __half* __restrict__ Bt, int ldb,
    float* __restrict__ C, int ldc,
    const float* __restrict__ bias, int act,
    const float* __restrict__ w2, const float* __restrict__ b2,
    long long strideA, long long strideB, long long strideC, int strideBias)
{
    extern __shared__ char smemc[];
    float* smem = (float*)smemc;
    const int tid  = threadIdx.x;
    const int wid  = tid>>5, lane = tid&31;
    const int bm   = blockIdx.y*128;
    const int bn   = blockIdx.x*128;
    const int zb   = blockIdx.z;
    A  += (size_t)zb*strideA;
    Bt += (size_t)zb*strideB;
    if(bias && act!=3) bias += (size_t)zb*strideBias;

    const int wm0 = (wid>>2)*64;
    const int wn0 = (wid&3)*32;
    const int gid = lane>>2;
    const int tig = lane&3;

    uint32_t sbase = smem_u32(smemc);
    const __half* Abase = A + (size_t)bm*lda;
    const __half* Bbase = Bt + (size_t)bn*ldb;
    const int KL = K >> 6;     // BK=64

    float acc[4][4][4];
#pragma unroll
    for(int i=0;i<4;i++)
#pragma unroll
        for(int j=0;j<4;j++)
#pragma unroll
            for(int q=0;q<4;q++) acc[i][j][q]=0.f;

    tg_load(sbase,              sbase + STG_A,              Abase,    lda, Bbase,    ldb, tid);
    tg_load(sbase + STG_BYTES,  sbase + STG_BYTES + STG_A,  Abase+64, lda, Bbase+64, ldb, tid);

    // hoisted per-thread fragment offsets (within a stage)
    const int rA  = wm0 + (lane&15);
    const int cA0 = lane>>4;
    const int xA  = rA & 7;
    const int rB  = wn0 + (lane&7) + ((lane>>4)&1)*8;
    const int cB0 = (lane>>3)&1;
    const int xB  = rB & 7;
    uint32_t offA[4], offB[4];
#pragma unroll
    for(int kst=0; kst<4; kst++){
        offA[kst] = (uint32_t)rA*128 + (uint32_t)(((cA0 + kst*2) ^ xA)*16);
        offB[kst] = (uint32_t)rB*128 + (uint32_t)(((cB0 + kst*2) ^ xB)*16);
    }

    for(int kc=0; kc<KL; kc++){
        if(kc+1<KL) asm volatile("cp.async.wait_group 1;" ::: "memory");
        else        asm volatile("cp.async.wait_group 0;" ::: "memory");
        __syncthreads();
        if(kc+2 < KL){
            int ns = kc+2; ns -= (ns/3)*3;
            tg_load(sbase + ns*STG_BYTES, sbase + ns*STG_BYTES + STG_A,
                    Abase + (kc+2)*64, lda, Bbase + (kc+2)*64, ldb, tid);
        }
        int s = kc - (kc/3)*3;
        uint32_t sA = sbase + s*STG_BYTES;
        uint32_t sB = sA + STG_A;
#pragma unroll
        for(int kst=0; kst<4; kst++){
            uint32_t aT = sA + offA[kst];
            uint32_t bT = sB + offB[kst];
            uint32_t af[4][4], bf[4][2];
#pragma unroll
            for(int mt=0; mt<4; mt++)
                ldsm4(af[mt], aT + mt*16*128);
#pragma unroll
            for(int p=0; p<2; p++){
                uint32_t t4[4];
                ldsm4(t4, bT + p*16*128);
                bf[2*p][0]=t4[0];   bf[2*p][1]=t4[1];
                bf[2*p+1][0]=t4[2]; bf[2*p+1][1]=t4[3];
            }
#pragma unroll
            for(int mt=0; mt<4; mt++)
#pragma unroll
                for(int nt=0; nt<4; nt++)
                    mma_f16(acc[mt][nt], af[mt], bf[nt]);
        }
    }
    __syncthreads();

    if(act==2){
        // fused attn score partial (128 cols); head = blockIdx.x>>1; C pre-init w/ b2
        float rsum[4][2];
#pragma unroll
        for(int mt=0;mt<4;mt++){ rsum[mt][0]=0.f; rsum[mt][1]=0.f; }
#pragma unroll
        for(int nt=0; nt<4; nt++){
            int gcol = bn + wn0 + nt*8 + tig*2;
            float b0v = bias[gcol], b1v = bias[gcol+1];
            float w0  = w2[gcol],  w1  = w2[gcol+1];
#pragma unroll
            for(int mt=0; mt<4; mt++){
                rsum[mt][0] += gelu_f(acc[mt][nt][0]+b0v)*w0 + gelu_f(acc[mt][nt][1]+b1v)*w1;
                rsum[mt][1] += gelu_f(acc[mt][nt][2]+b0v)*w0 + gelu_f(acc[mt][nt][3]+b1v)*w1;
            }
        }
#pragma unroll
        for(int mt=0; mt<4; mt++)
#pragma unroll
            for(int hh=0; hh<2; hh++){
                rsum[mt][hh] += __shfl_xor_sync(0xffffffffu, rsum[mt][hh], 1);
                rsum[mt][hh] += __shfl_xor_sync(0xffffffffu, rsum[mt][hh], 2);
            }
        float* red = smem;
        if(tig==0){
#pragma unroll
            for(int mt=0; mt<4; mt++)
#pragma unroll
                for(int hh=0; hh<2; hh++)
                    red[(wid&3)*128 + wm0 + mt*16 + hh*8 + gid] = rsum[mt][hh];
        }
        __syncthreads();
        if(tid < 128){
            float sv = red[tid] + red[128+tid] + red[256+tid] + red[384+tid];
            atomicAdd(&C[(size_t)(blockIdx.x>>1)*MM + bm + tid], sv);
        }
        return;
    }

    if(act==3){
        // FiLM K=512 algebra:
        // gamma = rstd*(acc_g + v0g + bs*v1g - mu*v2g) + v3g; beta analogous (+512 col)
        const __half* nh = (const __half*)w2;
        const float4* st = (const float4*)bias;
        const float* v = b2;     // [4][1024]
        __half* Ch = (__half*)C;
#pragma unroll
        for(int mt=0; mt<4; mt++){
            int r0 = bm + wm0 + mt*16 + gid;
            float4 s0 = st[r0];
            float4 s1 = st[r0+8];
#pragma unroll
            for(int nt=0; nt<4; nt++){
                int c0 = bn + wn0 + nt*8 + tig*2;
                int j  = c0 >> 1;
                float v0g=v[j],      v1g=v[1024+j], v2g=v[2048+j], v3g=v[3072+j];
                float v0b=v[512+j],  v1b=v[1536+j], v2b=v[2560+j], v3b=v[3584+j];
                float gam0 = s0.z*(acc[mt][nt][0] + v0g + s0.x*v1g - s0.y*v2g) + v3g;
                float bet0 = s0.z*(acc[mt][nt][1] + v0b + s0.x*v1b - s0.y*v2b) + v3b;
                float gam1 = s1.z*(acc[mt][nt][2] + v0g + s1.x*v1g - s1.y*v2g) + v3g;
                float bet1 = s1.z*(acc[mt][nt][3] + v0b + s1.x*v1b - s1.y*v2b) + v3b;
                float nh0 = __half2float(nh[(size_t)r0*DD + j]);
                float nh1 = __half2float(nh[(size_t)(r0+8)*DD + j]);
                Ch[(size_t)r0*ldc + j]     = __float2half_rn(fmaf(nh0, 1.f+gam0, bet0));
                Ch[(size_t)(r0+8)*ldc + j] = __float2half_rn(fmaf(nh1, 1.f+gam1, bet1));
            }
        }
        return;
    }

    if(act==1){
        __half* Ch = (__half*)C + (size_t)zb*strideC;
#pragma unroll
        for(int mt=0; mt<4; mt++){
            int r0 = bm + wm0 + mt*16 + gid;
#pragma unroll
            for(int nt=0; nt<4; nt++){
                int col = bn + wn0 + nt*8 + tig*2;
                float b0v = bias[col], b1v = bias[col+1];
                __half2 o0 = __floats2half2_rn(gelu_f(acc[mt][nt][0]+b0v),
                                               gelu_f(acc[mt][nt][1]+b1v));
                __half2 o1 = __floats2half2_rn(gelu_f(acc[mt][nt][2]+b0v),
                                               gelu_f(acc[mt][nt][3]+b1v));
                *(__half2*)(Ch + (size_t)r0*ldc + col)     = o0;
                *(__half2*)(Ch + (size_t)(r0+8)*ldc + col) = o1;
            }
        }
        return;
    }

    if(act==4){
        int vocab = (zb==0) ? 64 : (zb==3) ? 25 : 13;
        int off   = (zb==0) ? 0 : (zb==1) ? 64 : (zb==2) ? 77 : 90;
#pragma unroll
        for(int mt=0; mt<4; mt++){
            int r0 = bm + wm0 + mt*16 + gid;
#pragma unroll
            for(int nt=0; nt<4; nt++){
                int col = wn0 + nt*8 + tig*2;
                if(col < vocab){
                    C[(size_t)r0*ldc + off + col]     = acc[mt][nt][0] + bias[col];
                    C[(size_t)(r0+8)*ldc + off + col] = acc[mt][nt][2] + bias[col];
                }
                if(col+1 < vocab){
                    C[(size_t)r0*ldc + off + col+1]     = acc[mt][nt][1] + bias[col+1];
                    C[(size_t)(r0+8)*ldc + off + col+1] = acc[mt][nt][3] + bias[col+1];
                }
            }
        }
        return;
    }

    C += (size_t)zb*strideC;
#pragma unroll
    for(int mt=0; mt<4; mt++){
        int r0 = bm + wm0 + mt*16 + gid;
#pragma unroll
        for(int nt=0; nt<4; nt++){
            int col = bn + wn0 + nt*8 + tig*2;
            float2 v0 = make_float2(acc[mt][nt][0], acc[mt][nt][1]);
            float2 v1 = make_float2(acc[mt][nt][2], acc[mt][nt][3]);
            if(bias){
                float b0v = bias[col], b1v = bias[col+1];
                v0.x += b0v; v0.y += b1v; v1.x += b0v; v1.y += b1v;
            }
            *(float2*)(C + (size_t)r0*ldc + col)     = v0;
            *(float2*)(C + (size_t)(r0+8)*ldc + col) = v1;
        }
    }
}

// init score array: dst[k*MM + t] = b2[k]
__global__ void k_sinit(float* __restrict__ dst, const float* __restrict__ b2){
    int i = blockIdx.x*256 + threadIdx.x;
    dst[i] = b2[i >> 14];
}

// parallel GEMV: v0..v3 film-algebra vectors; one block per output column j
__global__ void k_gemv(const float* __restrict__ film_w,
                       const float* __restrict__ e0, const float* __restrict__ e1,
                       const float* __restrict__ g,  const float* __restrict__ bb,
                       const float* __restrict__ film_b){
    __shared__ float red[4][8];
    int j = blockIdx.x;
    int tid = threadIdx.x;
    int lane = tid&31, wid = tid>>5;
    float a0=0.f, a1=0.f, a2=0.f, a3=0.f;
    for(int i=tid; i<DIN; i+=256){
        float w  = film_w[(size_t)i*1024 + j];
        float gi = g[i];
        if(i>=DD){
            float ev = e0[i-DD];
            a0 = fmaf(ev*gi, w, a0);
            a1 = fmaf((e1[i-DD]-ev)*gi, w, a1);
        }
        a2 = fmaf(gi, w, a2);
        a3 = fmaf(bb[i], w, a3);
    }
    a0 = warp_sum(a0); a1 = warp_sum(a1); a2 = warp_sum(a2); a3 = warp_sum(a3);
    if(lane==0){ red[0][wid]=a0; red[1][wid]=a1; red[2][wid]=a2; red[3][wid]=a3; }
    __syncthreads();
    if(tid < 4){
        float s = 0.f;
#pragma unroll
        for(int w=0; w<8; w++) s += red[tid][w];
        if(tid==3) s += film_b[j];
        g_v[tid*1024 + j] = s;
    }
}

// ================= fused prep =================
__device__ __forceinline__ void do_transpose(const float* __restrict__ src,
                                             __half* __restrict__ dst,
                                             int R, int C, int bx, int by,
                                             float tile[32][33]){
    int c0 = bx*32, r0 = by*32;
    int tx = threadIdx.x, ty = threadIdx.y;
#pragma unroll
    for(int i=0;i<32;i+=8)
        tile[ty+i][tx] = src[(size_t)(r0+ty+i)*C + c0+tx];
    __syncthreads();
#pragma unroll
    for(int i=0;i<32;i+=8)
        dst[(size_t)(c0+ty+i)*R + r0+tx] = __float2half_rn(tile[tx][ty+i]);
}

// blocks: [0,512) film-head; [512,1024) attn; [1024,2048) proj; [2048,10240) h; [10240,10752) wc
__global__ void k_prep(const float* __restrict__ film_w,
                       const float* __restrict__ attn_w1,
                       const float* __restrict__ proj_w1,
                       const float* __restrict__ h,
                       const float* __restrict__ w2q, const float* __restrict__ b2q,
                       const float* __restrict__ w2r, const float* __restrict__ b2r,
                       const float* __restrict__ w2b, const float* __restrict__ b2b,
                       const float* __restrict__ w2k, const float* __restrict__ b2k){
    __shared__ float tile[32][33];
    int b = blockIdx.x;
    if(b < 512){
        int bx = b&31, by = b>>5;
        int c0 = bx*32, r0 = by*32;
        int tx = threadIdx.x, ty = threadIdx.y;
#pragma unroll
        for(int i=0;i<32;i+=8)
            tile[ty+i][tx] = film_w[(size_t)(r0+ty+i)*1024 + c0+tx];
        __syncthreads();
#pragma unroll
        for(int i=0;i<32;i+=8){
            int c = c0+ty+i;
            int ic = (c<512) ? 2*c : 2*(c-512)+1;
            g_wt_film[(size_t)ic*DD + r0+tx] = __float2half_rn(tile[tx][ty+i]);
        }
    } else if(b < 1024){
        int bb = b - 512;
        int k  = bb >> 7; bb &= 127;
        do_transpose(attn_w1 + (size_t)k*DD*256, g_wt_attn + (size_t)k*256*DD,
                     DD, 256, bb&7, bb>>3, tile);
    } else if(b < 2048){
        int bb = b - 1024;
        int k  = bb >> 8; bb &= 255;
        do_transpose(proj_w1 + (size_t)k*DD*DD, g_wt_proj + (size_t)k*DD*DD,
                     DD, 512, bb&15, bb>>4, tile);
    } else if(b < 10240){
        int bb = b - 2048;
        int tid = threadIdx.y*32 + threadIdx.x;
        size_t i = (size_t)bb*1024 + tid*4;
        float4 v = *(const float4*)(h + i);
        __half2 h0 = __floats2half2_rn(v.x, v.y);
        __half2 h1 = __floats2half2_rn(v.z, v.w);
        *(__half2*)(g_ht + i)     = h0;
        *(__half2*)(g_ht + i + 2) = h1;
    } else {
        int c = b - 10240;
        int k = c >> 7, r = c & 127;
        int tid = threadIdx.y*32 + threadIdx.x;
        int vocab; const float *W, *bs2;
        if(k==0)      { vocab=64; W=w2q; bs2=b2q; }
        else if(k==1) { vocab=13; W=w2r; bs2=b2r; }
        else if(k==2) { vocab=13; W=w2b; bs2=b2b; }
        else          { vocab=25; W=w2k; bs2=b2k; }
        for(int d=tid; d<DD; d+=256){
            float val = (r < vocab) ? W[(size_t)d*vocab + r] : 0.f;
            g_wc[((size_t)k*128 + r)*DD + d] = __float2half_rn(val);
        }
        if(tid == 0) g_bc[k*128 + r] = (r < vocab) ? bs2[r] : 0.f;
    }
}

// ================= stage 1: bl = h . w_bnd + b =================
__global__ void k_bl(const float* __restrict__ h, const float* __restrict__ w,
                     const float* __restrict__ b0, float* __restrict__ out){
    int t    = blockIdx.x*8 + (threadIdx.x>>5);
    int lane = threadIdx.x&31;
    const float4* hr = (const float4*)(h + (size_t)t*DD);
    const float4* w4 = (const float4*)w;
    float acc = 0.f;
#pragma unroll
    for(int i=0;i<4;i++){
        float4 a = hr[lane + i*32];
        float4 b = w4[lane + i*32];
        acc += a.x*b.x + a.y*b.y + a.z*b.z + a.w*b.w;
    }
    acc = warp_sum(acc);
    if(lane==0){
        float v = acc + b0[0];
        g_bl[t] = v;
        out[(size_t)t*NCOL + 115] = v;
    }
}

// ================= stage 2: conv + sigmoid =================
__global__ void k_bsoft(const float* __restrict__ ck, const float* __restrict__ cb){
    int t  = blockIdx.x*256 + threadIdx.x;
    int b  = t / TT, tt = t - b*TT;
    float acc = cb[0];
#pragma unroll
    for(int j=0;j<9;j++){
        int tj = tt + j - 4;
        if(tj>=0 && tj<TT) acc = fmaf(g_bl[b*TT+tj], ck[j], acc);
    }
    g_bsoft[t] = 1.f/(1.f + expf(-acc));
}

// ================= stage 3: stats + hg + nh (+ sz init) =================
__global__ void k_filmin(const float* __restrict__ h, const float* __restrict__ e0,
                         const float* __restrict__ e1, const float* __restrict__ g,
                         const float* __restrict__ lng, const float* __restrict__ lnb,
                         const float* __restrict__ b2a){
    __shared__ float rbuf[4][8];
    int t = blockIdx.x;
    int lane = threadIdx.x&31, wid = threadIdx.x>>5;
    float bs = g_bsoft[t];
    const float* hr = h + (size_t)t*DD;
    float v[3];
#pragma unroll
    for(int c=0;c<3;c++){
        int i = threadIdx.x + c*256;
        float val = 0.f;
        if(i < DIN) val = (i < DD) ? hr[i] : (bs*e1[i-DD] + (1.f-bs)*e0[i-DD]);
        v[c] = val;
    }
    float s4[4];
    s4[0] = v[0]+v[1]+v[2];
    s4[1] = v[0]*v[0]+v[1]*v[1]+v[2]*v[2];
    s4[2] = v[0]+v[1];
    s4[3] = v[0]*v[0]+v[1]*v[1];
#pragma unroll
    for(int q=0;q<4;q++){
        s4[q] = warp_sum(s4[q]);
        if(lane==0) rbuf[q][wid] = s4[q];
    }
    __syncthreads();
    if(wid==0){
#pragma unroll
        for(int q=0;q<4;q++){
            float s = (lane<8)? rbuf[q][lane] : 0.f;
            s = warp_sum(s);
            if(lane==0) rbuf[q][0] = s;
        }
    }
    __syncthreads();
    float mu  = rbuf[0][0] / (float)DIN;
    float var = rbuf[1][0] / (float)DIN - mu*mu;
    float rstd = rsqrtf(var + 1e-5f);
    float muh  = rbuf[2][0] / (float)DD;
    float varh = rbuf[3][0] / (float)DD - muh*muh;
    float rstdh = rsqrtf(varh + 1e-5f);
    if(threadIdx.x == 0) g_st[t] = make_float4(bs, mu, rstd, 0.f);
    if(threadIdx.x < 4)  g_sz[(size_t)threadIdx.x*MM + t] = b2a[threadIdx.x];
#pragma unroll
    for(int c=0;c<2;c++){
        int i = threadIdx.x + c*256;
        g_filmin[(size_t)t*DD + i] = __float2half_rn(v[c]*g[i]);           // hg
        g_nh[(size_t)t*DD + i]     = __float2half_rn((v[c]-muh)*rstdh*lng[i] + lnb[i]);
    }
}

// ================= stage 8: softmax + pool =================
__global__ void k_pool(){
    __shared__ float sa[4][10];
    __shared__ int   sidx[9];
    int t = blockIdx.x;
    int b = t/TT, tt = t - b*TT;
    int tid = threadIdx.x;
    if(tid < 9){
        int tj = tt + tid - 4;
        tj = min(max(tj, 0), TT-1);
        sidx[tid] = b*TT + tj;
    }
    __syncthreads();
    if(tid < 4){
        int k = tid;
        float sc[10];
        sc[0] = g_sz[(size_t)k*MM + t];
#pragma unroll
        for(int j=0;j<9;j++) sc[1+j] = g_sh[(size_t)k*MM + sidx[j]];
        float mx = sc[0];
#pragma unroll
        for(int c=1;c<10;c++) mx = fmaxf(mx, sc[c]);
        float sum = 0.f;
#pragma unroll
        for(int c=0;c<10;c++){ sc[c] = expf(sc[c]-mx); sum += sc[c]; }
        float inv = 1.f/sum;
#pragma unroll
        for(int c=0;c<10;c++) sa[k][c] = sc[c]*inv;
    }
    __syncthreads();
    int d = tid*4;
    const __half2* zp = (const __half2*)(g_z + (size_t)t*DD + d);
    float2 zlo = __half22float2(zp[0]);
    float2 zhi = __half22float2(zp[1]);
    float4 zv = make_float4(zlo.x, zlo.y, zhi.x, zhi.y);
    float4 hv[9];
#pragma unroll
    for(int j=0;j<9;j++){
        const __half2* hp = (const __half2*)(g_ht + (size_t)sidx[j]*DD + d);
        float2 lo = __half22float2(hp[0]);
        float2 hi = __half22float2(hp[1]);
        hv[j] = make_float4(lo.x, lo.y, hi.x, hi.y);
    }
#pragma unroll
    for(int k=0;k<4;k++){
        float4 p;
        p.x = sa[k][0]*zv.x; p.y = sa[k][0]*zv.y;
        p.z = sa[k][0]*zv.z; p.w = sa[k][0]*zv.w;
#pragma unroll
        for(int j=0;j<9;j++){
            float w = sa[k][1+j];
            p.x = fmaf(w, hv[j].x, p.x); p.y = fmaf(w, hv[j].y, p.y);
            p.z = fmaf(w, hv[j].z, p.z); p.w = fmaf(w, hv[j].w, p.w);
        }
        __half2 o0 = __floats2half2_rn(p.x, p.y);
        __half2 o1 = __floats2half2_rn(p.z, p.w);
        __half2* op = (__half2*)(g_pool + ((size_t)k*MM + t)*DD + d);
        op[0] = o0; op[1] = o1;
    }
}

// ================= launch =================
extern "C" void kernel_launch(void* const* d_in, const int* in_sizes, int n_in,
                              void* d_out, int out_size){
    const float* h       = (const float*)d_in[0];
    const float* w_bnd   = (const float*)d_in[1];
    const float* b_bnd   = (const float*)d_in[2];
    const float* conv_k  = (const float*)d_in[3];
    const float* conv_b  = (const float*)d_in[4];
    const float* e0      = (const float*)d_in[5];
    const float* e1      = (const float*)d_in[6];
    const float* ln_in_g = (const float*)d_in[7];
    const float* ln_in_b = (const float*)d_in[8];
    const float* ln_h_g  = (const float*)d_in[9];
    const float* ln_h_b  = (const float*)d_in[10];
    const float* film_w  = (const float*)d_in[11];
    const float* film_b  = (const float*)d_in[12];
    const float* attn_w1 = (const float*)d_in[13];
    const float* attn_b1 = (const float*)d_in[14];
    const float* attn_w2 = (const float*)d_in[15];
    const float* attn_b2 = (const float*)d_in[16];
    const float* proj_w1 = (const float*)d_in[17];
    const float* proj_b1 = (const float*)d_in[18];
    const float* w2q = (const float*)d_in[19]; const float* b2q = (const float*)d_in[20];
    const float* w2r = (const float*)d_in[21]; const float* b2r = (const float*)d_in[22];
    const float* w2b = (const float*)d_in[23]; const float* b2b = (const float*)d_in[24];
    const float* w2k = (const float*)d_in[25]; const float* b2k = (const float*)d_in[26];
    float* out = (float*)d_out;

    __half *p_filmin, *p_nh, *p_z, *p_ht, *p_pool, *p_p1, *p_wtf, *p_wta, *p_wtp, *p_wc;
    float  *p_sh, *p_sz, *p_bc, *p_v, *p_st;
    cudaGetSymbolAddress((void**)&p_filmin, g_filmin);
    cudaGetSymbolAddress((void**)&p_nh,     g_nh);
    cudaGetSymbolAddress((void**)&p_z,      g_z);
    cudaGetSymbolAddress((void**)&p_ht,     g_ht);
    cudaGetSymbolAddress((void**)&p_sh,     g_sh);
    cudaGetSymbolAddress((void**)&p_sz,     g_sz);
    cudaGetSymbolAddress((void**)&p_pool,   g_pool);
    cudaGetSymbolAddress((void**)&p_p1,     g_p1);
    cudaGetSymbolAddress((void**)&p_wtf,    g_wt_film);
    cudaGetSymbolAddress((void**)&p_wta,    g_wt_attn);
    cudaGetSymbolAddress((void**)&p_wtp,    g_wt_proj);
    cudaGetSymbolAddress((void**)&p_wc,     g_wc);
    cudaGetSymbolAddress((void**)&p_bc,     g_bc);
    cudaGetSymbolAddress((void**)&p_v,      g_v);
    cudaGetSymbolAddress((void**)&p_st,     g_st);

    cudaFuncSetAttribute(tgemm, cudaFuncAttributeMaxDynamicSharedMemorySize, TG_SMEM);

    cudaStream_t s2 = g_ss.s2;

    // ---- fork side stream ----
    cudaEventRecord(g_ss.evF, 0);
    cudaStreamWaitEvent(s2, g_ss.evF, 0);

    // [1] prep (s2)
    k_prep<<<10752, dim3(32,8), 0, s2>>>(film_w, attn_w1, proj_w1, h,
                                         w2q, b2q, w2r, b2r, w2b, b2b, w2k, b2k);
    // [2] init g_sh (s2)
    k_sinit<<<4*MM/256, 256, 0, s2>>>(p_sh, attn_b2);
    cudaEventRecord(g_ss.evP, s2);
    // [3] gemv (main, off s2 critical path; done long before film GEMM)
    k_gemv<<<1024, 256>>>(film_w, e0, e1, ln_in_g, ln_in_b, film_b);
    // [4] hW1 + fused score (s2)
    tgemm<<<dim3(1024/128, MM/128, 1), 256, TG_SMEM, s2>>>(
        DD, p_ht, DD, p_wta, DD, p_sh, MM, attn_b1, 2,
        attn_w2, attn_b2, 0,0,0,0);
    cudaEventRecord(g_ss.evH, s2);
    // [5] bl (main)
    k_bl<<<MM/8, 256>>>(h, w_bnd, b_bnd, out);
    // [6] bsoft (main)
    k_bsoft<<<MM/256, 256>>>(conv_k, conv_b);
    // [7] filmin (main): stats + hg + nh + sz init
    k_filmin<<<MM, 256>>>(h, e0, e1, ln_in_g, ln_h_g, ln_h_b, attn_b2);

    // [8] film GEMM (K=512) + fused z (needs prep weights + gemv vectors)
    cudaStreamWaitEvent(0, g_ss.evP, 0);
    tgemm<<<dim3(1024/128, MM/128, 1), 256, TG_SMEM>>>(
        DD, p_filmin, DD, p_wtf, DD, (float*)p_z, DD, p_st, 3,
        (const float*)p_nh, p_v, 0,0,0,0);
    // [9] zW1 + fused score
    tgemm<<<dim3(1024/128, MM/128, 1), 256, TG_SMEM>>>(
        DD, p_z, DD, p_wta, DD, p_sz, MM, attn_b1, 2,
        attn_w2, attn_b2, 0,0,0,0);

    // join: pool needs g_sh
    cudaStreamWaitEvent(0, g_ss.evH, 0);
    // [10] pool
    k_pool<<<MM, 128>>>();
    // [11] proj (4 heads via blockIdx.z), half output in [MM,2048] layout
    tgemm<<<dim3(512/128, MM/128, 4), 256, TG_SMEM>>>(
        DD, p_pool, DD, p_wtp, DD, (float*)p_p1, 2048, proj_b1, 1,
        nullptr, nullptr,
        (long long)MM*DD, (long long)DD*DD, 512LL, DD);
    // [12] vocab heads: 4 z-batched per-head GEMMs [MM,512]x[512,128]
    tgemm<<<dim3(1, MM/128, 4), 256, TG_SMEM>>>(
        DD, p_p1, 2048, p_wc, DD, out, NCOL, p_bc, 4,
        nullptr, nullptr, 512LL, (long long)128*DD, 0, 128);
}

// round 16
// speedup vs baseline: 1.5777x; 1.0525x over previous
#include <cuda_runtime.h>
#include <cuda_fp16.h>
#include <math.h>
#include <stdint.h>

#define BB   4
#define TT   4096
#define DD   512
#define MM   (BB*TT)        // 16384 tokens
#define DIN  640            // D + DB
#define NCOL 116

// ---------------- scratch ----------------
__device__ float  g_bl[MM];
__device__ float  g_bsoft[MM];
__device__ __half g_filmin[(size_t)MM*DD];     // hg = h*g_head (K=512)
__device__ __half g_nh[(size_t)MM*DD];
__device__ __half g_z[(size_t)MM*DD];
__device__ __half g_ht[(size_t)MM*DD];
__device__ float4 g_st[MM];                    // (bs, mu, rstd, 0)
__device__ float  g_v[4*1024];                 // v0,v1,v2,v3
__device__ float  g_sh[(size_t)4*MM];
__device__ float  g_sz[(size_t)4*MM];
__device__ __half g_pool[(size_t)4*MM*DD];
__device__ __half g_p1[(size_t)MM*2048];
__device__ __half g_wt_film[(size_t)1024*DD];  // W_head^T, gamma/beta interleaved rows
__device__ __half g_wt_attn[(size_t)1024*DD];
__device__ __half g_wt_proj[(size_t)2048*DD];
__device__ __half g_wc[(size_t)4*128*DD];
__device__ float  g_bc[4*128];

// ---------------- side stream ----------------
struct SideStream {
    cudaStream_t s2;
    cudaEvent_t evF, evP, evH, evM, evJ;
    SideStream(){
        cudaStreamCreateWithFlags(&s2, cudaStreamNonBlocking);
        cudaEventCreateWithFlags(&evF, cudaEventDisableTiming);
        cudaEventCreateWithFlags(&evP, cudaEventDisableTiming);
        cudaEventCreateWithFlags(&evH, cudaEventDisableTiming);
        cudaEventCreateWithFlags(&evM, cudaEventDisableTiming);
        cudaEventCreateWithFlags(&evJ, cudaEventDisableTiming);
    }
};
static SideStream g_ss;

// ================= helpers =================
__device__ __forceinline__ void cp16(uint32_t dst, const void* src){
    asm volatile("cp.async.cg.shared.global [%0], [%1], 16;" :: "r"(dst), "l"(src));
}
__device__ __forceinline__ uint32_t smem_u32(const void* p){
    uint32_t a;
    asm("{ .reg .u64 t; cvta.to.shared.u64 t, %1; cvt.u32.u64 %0, t; }" : "=r"(a) : "l"(p));
    return a;
}
__device__ __forceinline__ float gelu_f(float x){
    return 0.5f*x*(1.0f+erff(x*0.70710678118654752440f));
}
__device__ __forceinline__ float warp_sum(float v){
#pragma unroll
    for(int o=16;o;o>>=1) v += __shfl_xor_sync(0xffffffffu, v, o);
    return v;
}
__device__ __forceinline__ void mma_f16(float* c, const uint32_t* a, const uint32_t* b){
    asm volatile(
        "mma.sync.aligned.m16n8k16.row.col.f32.f16.f16.f32 "
        "{%0,%1,%2,%3}, {%4,%5,%6,%7}, {%8,%9}, {%0,%1,%2,%3};"
        : "+f"(c[0]), "+f"(c[1]), "+f"(c[2]), "+f"(c[3])
        : "r"(a[0]), "r"(a[1]), "r"(a[2]), "r"(a[3]), "r"(b[0]), "r"(b[1]));
}
__device__ __forceinline__ void ldsm4(uint32_t* r, uint32_t addr){
    asm volatile("ldmatrix.sync.aligned.m8n8.x4.shared.b16 {%0,%1,%2,%3}, [%4];"
        : "=r"(r[0]), "=r"(r[1]), "=r"(r[2]), "=r"(r[3]) : "r"(addr));
}

// ================= FP16 mma.sync GEMM, 128x128 tile, BK=64, XOR swizzle, 3 stages, occ=2 =================
// act: 0=f32, 1=gelu->half (p1 layout), 2=attn score (atomicAdd),
//      3=FiLM z->half (K=512 algebra), 4=per-head vocab out
// mOff: row offset added to bm (for M-split chains)
#define STG_A 16384
#define STG_BYTES 32768
#define TG_SMEM (3*STG_BYTES)      // 98304 -> 2 CTAs/SM

__device__ __forceinline__ void tg_load(uint32_t sA, uint32_t sB,
                                        const __half* Ap, int lda,
                                        const __half* Bp, int ldb, int tid){
#pragma unroll
    for(int i=0;i<4;i++){
        int idx = tid + i*256;
        int row = idx>>3, cw = idx&7;
        uint32_t off = row*128 + ((cw ^ (row&7))*16);
        cp16(sA + off, Ap + (size_t)row*lda + cw*8);
    }
#pragma unroll
    for(int i=0;i<4;i++){
        int idx = tid + i*256;
        int row = idx>>3, cw = idx&7;
        uint32_t off = row*128 + ((cw ^ (row&7))*16);
        cp16(sB + off, Bp + (size_t)row*ldb + cw*8);
    }
    asm volatile("cp.async.commit_group;" ::: "memory");
}

__global__ void __launch_bounds__(256, 2) tgemm(
    int K, const __half* __restrict__ A, int lda,
    const __half* __restrict__ Bt, int ldb,
    float* __restrict__ C, int ldc,
    const float* __restrict__ bias, int act,
    const float* __restrict__ w2, const float* __restrict__ b2,
    long long strideA, long long strideB, long long strideC, int strideBias,
    int mOff)
{
    extern __shared__ char smemc[];
    float* smem = (float*)smemc;
    const int tid  = threadIdx.x;
    const int wid  = tid>>5, lane = tid&31;
    const int bm   = blockIdx.y*128 + mOff;
    const int bn   = blockIdx.x*128;
    const int zb   = blockIdx.z;
    A  += (size_t)zb*strideA;
    Bt += (size_t)zb*strideB;
    if(bias && act!=3) bias += (size_t)zb*strideBias;

    const int wm0 = (wid>>2)*64;
    const int wn0 = (wid&3)*32;
    const int gid = lane>>2;
    const int tig = lane&3;

    uint32_t sbase = smem_u32(smemc);
    const __half* Abase = A + (size_t)bm*lda;
    const __half* Bbase = Bt + (size_t)bn*ldb;
    const int KL = K >> 6;     // BK=64

    float acc[4][4][4];
#pragma unroll
    for(int i=0;i<4;i++)
#pragma unroll
        for(int j=0;j<4;j++)
#pragma unroll
            for(int q=0;q<4;q++) acc[i][j][q]=0.f;

    tg_load(sbase,              sbase + STG_A,              Abase,    lda, Bbase,    ldb, tid);
    tg_load(sbase + STG_BYTES,  sbase + STG_BYTES + STG_A,  Abase+64, lda, Bbase+64, ldb, tid);

    const int rA  = wm0 + (lane&15);
    const int cA0 = lane>>4;
    const int xA  = rA & 7;
    const int rB  = wn0 + (lane&7) + ((lane>>4)&1)*8;
    const int cB0 = (lane>>3)&1;
    const int xB  = rB & 7;
    uint32_t offA[4], offB[4];
#pragma unroll
    for(int kst=0; kst<4; kst++){
        offA[kst] = (uint32_t)rA*128 + (uint32_t)(((cA0 + kst*2) ^ xA)*16);
        offB[kst] = (uint32_t)rB*128 + (uint32_t)(((cB0 + kst*2) ^ xB)*16);
    }

    for(int kc=0; kc<KL; kc++){
        if(kc+1<KL) asm volatile("cp.async.wait_group 1;" ::: "memory");
        else        asm volatile("cp.async.wait_group 0;" ::: "memory");
        __syncthreads();
        if(kc+2 < KL){
            int ns = kc+2; ns -= (ns/3)*3;
            tg_load(sbase + ns*STG_BYTES, sbase + ns*STG_BYTES + STG_A,
                    Abase + (kc+2)*64, lda, Bbase + (kc+2)*64, ldb, tid);
        }
        int s = kc - (kc/3)*3;
        uint32_t sA = sbase + s*STG_BYTES;
        uint32_t sB = sA + STG_A;
#pragma unroll
        for(int kst=0; kst<4; kst++){
            uint32_t aT = sA + offA[kst];
            uint32_t bT = sB + offB[kst];
            uint32_t af[4][4], bf[4][2];
#pragma unroll
            for(int mt=0; mt<4; mt++)
                ldsm4(af[mt], aT + mt*16*128);
#pragma unroll
            for(int p=0; p<2; p++){
                uint32_t t4[4];
                ldsm4(t4, bT + p*16*128);
                bf[2*p][0]=t4[0];   bf[2*p][1]=t4[1];
                bf[2*p+1][0]=t4[2]; bf[2*p+1][1]=t4[3];
            }
#pragma unroll
            for(int mt=0; mt<4; mt++)
#pragma unroll
                for(int nt=0; nt<4; nt++)
                    mma_f16(acc[mt][nt], af[mt], bf[nt]);
        }
    }
    __syncthreads();

    if(act==2){
        // fused attn score partial (128 cols); head = blockIdx.x>>1; C pre-init w/ b2
        float rsum[4][2];
#pragma unroll
        for(int mt=0;mt<4;mt++){ rsum[mt][0]=0.f; rsum[mt][1]=0.f; }
#pragma unroll
        for(int nt=0; nt<4; nt++){
            int gcol = bn + wn0 + nt*8 + tig*2;
            float b0v = bias[gcol], b1v = bias[gcol+1];
            float w0  = w2[gcol],  w1  = w2[gcol+1];
#pragma unroll
            for(int mt=0; mt<4; mt++){
                rsum[mt][0] += gelu_f(acc[mt][nt][0]+b0v)*w0 + gelu_f(acc[mt][nt][1]+b1v)*w1;
                rsum[mt][1] += gelu_f(acc[mt][nt][2]+b0v)*w0 + gelu_f(acc[mt][nt][3]+b1v)*w1;
            }
        }
#pragma unroll
        for(int mt=0; mt<4; mt++)
#pragma unroll
            for(int hh=0; hh<2; hh++){
                rsum[mt][hh] += __shfl_xor_sync(0xffffffffu, rsum[mt][hh], 1);
                rsum[mt][hh] += __shfl_xor_sync(0xffffffffu, rsum[mt][hh], 2);
            }
        float* red = smem;
        if(tig==0){
#pragma unroll
            for(int mt=0; mt<4; mt++)
#pragma unroll
                for(int hh=0; hh<2; hh++)
                    red[(wid&3)*128 + wm0 + mt*16 + hh*8 + gid] = rsum[mt][hh];
        }
        __syncthreads();
        if(tid < 128){
            float sv = red[tid] + red[128+tid] + red[256+tid] + red[384+tid];
            atomicAdd(&C[(size_t)(blockIdx.x>>1)*MM + bm + tid], sv);
        }
        return;
    }

    if(act==3){
        const __half* nh = (const __half*)w2;
        const float4* st = (const float4*)bias;
        const float* v = b2;
        __half* Ch = (__half*)C;
#pragma unroll
        for(int mt=0; mt<4; mt++){
            int r0 = bm + wm0 + mt*16 + gid;
            float4 s0 = st[r0];
            float4 s1 = st[r0+8];
#pragma unroll
            for(int nt=0; nt<4; nt++){
                int c0 = bn + wn0 + nt*8 + tig*2;
                int j  = c0 >> 1;
                float v0g=v[j],      v1g=v[1024+j], v2g=v[2048+j], v3g=v[3072+j];
                float v0b=v[512+j],  v1b=v[1536+j], v2b=v[2560+j], v3b=v[3584+j];
                float gam0 = s0.z*(acc[mt][nt][0] + v0g + s0.x*v1g - s0.y*v2g) + v3g;
                float bet0 = s0.z*(acc[mt][nt][1] + v0b + s0.x*v1b - s0.y*v2b) + v3b;
                float gam1 = s1.z*(acc[mt][nt][2] + v0g + s1.x*v1g - s1.y*v2g) + v3g;
                float bet1 = s1.z*(acc[mt][nt][3] + v0b + s1.x*v1b - s1.y*v2b) + v3b;
                float nh0 = __half2float(nh[(size_t)r0*DD + j]);
                float nh1 = __half2float(nh[(size_t)(r0+8)*DD + j]);
                Ch[(size_t)r0*ldc + j]     = __float2half_rn(fmaf(nh0, 1.f+gam0, bet0));
                Ch[(size_t)(r0+8)*ldc + j] = __float2half_rn(fmaf(nh1, 1.f+gam1, bet1));
            }
        }
        return;
    }

    if(act==1){
        __half* Ch = (__half*)C + (size_t)zb*strideC;
#pragma unroll
        for(int mt=0; mt<4; mt++){
            int r0 = bm + wm0 + mt*16 + gid;
#pragma unroll
            for(int nt=0; nt<4; nt++){
                int col = bn + wn0 + nt*8 + tig*2;
                float b0v = bias[col], b1v = bias[col+1];
                __half2 o0 = __floats2half2_rn(gelu_f(acc[mt][nt][0]+b0v),
                                               gelu_f(acc[mt][nt][1]+b1v));
                __half2 o1 = __floats2half2_rn(gelu_f(acc[mt][nt][2]+b0v),
                                               gelu_f(acc[mt][nt][3]+b1v));
                *(__half2*)(Ch + (size_t)r0*ldc + col)     = o0;
                *(__half2*)(Ch + (size_t)(r0+8)*ldc + col) = o1;
            }
        }
        return;
    }

    if(act==4){
        int vocab = (zb==0) ? 64 : (zb==3) ? 25 : 13;
        int off   = (zb==0) ? 0 : (zb==1) ? 64 : (zb==2) ? 77 : 90;
#pragma unroll
        for(int mt=0; mt<4; mt++){
            int r0 = bm + wm0 + mt*16 + gid;
#pragma unroll
            for(int nt=0; nt<4; nt++){
                int col = wn0 + nt*8 + tig*2;
                if(col < vocab){
                    C[(size_t)r0*ldc + off + col]     = acc[mt][nt][0] + bias[col];
                    C[(size_t)(r0+8)*ldc + off + col] = acc[mt][nt][2] + bias[col];
                }
                if(col+1 < vocab){
                    C[(size_t)r0*ldc + off + col+1]     = acc[mt][nt][1] + bias[col+1];
                    C[(size_t)(r0+8)*ldc + off + col+1] = acc[mt][nt][3] + bias[col+1];
                }
            }
        }
        return;
    }

    C += (size_t)zb*strideC;
#pragma unroll
    for(int mt=0; mt<4; mt++){
        int r0 = bm + wm0 + mt*16 + gid;
#pragma unroll
        for(int nt=0; nt<4; nt++){
            int col = bn + wn0 + nt*8 + tig*2;
            float2 v0 = make_float2(acc[mt][nt][0], acc[mt][nt][1]);
            float2 v1 = make_float2(acc[mt][nt][2], acc[mt][nt][3]);
            if(bias){
                float b0v = bias[col], b1v = bias[col+1];
                v0.x += b0v; v0.y += b1v; v1.x += b0v; v1.y += b1v;
            }
            *(float2*)(C + (size_t)r0*ldc + col)     = v0;
            *(float2*)(C + (size_t)(r0+8)*ldc + col) = v1;
        }
    }
}

// init score array: dst[k*MM + t] = b2[k]
__global__ void k_sinit(float* __restrict__ dst, const float* __restrict__ b2){
    int i = blockIdx.x*256 + threadIdx.x;
    dst[i] = b2[i >> 14];
}

// parallel GEMV: v0..v3 film-algebra vectors; one block per output column j
__global__ void k_gemv(const float* __restrict__ film_w,
                       const float* __restrict__ e0, const float* __restrict__ e1,
                       const float* __restrict__ g,  const float* __restrict__ bb,
                       const float* __restrict__ film_b){
    __shared__ float red[4][8];
    int j = blockIdx.x;
    int tid = threadIdx.x;
    int lane = tid&31, wid = tid>>5;
    float a0=0.f, a1=0.f, a2=0.f, a3=0.f;
    for(int i=tid; i<DIN; i+=256){
        float w  = film_w[(size_t)i*1024 + j];
        float gi = g[i];
        if(i>=DD){
            float ev = e0[i-DD];
            a0 = fmaf(ev*gi, w, a0);
            a1 = fmaf((e1[i-DD]-ev)*gi, w, a1);
        }
        a2 = fmaf(gi, w, a2);
        a3 = fmaf(bb[i], w, a3);
    }
    a0 = warp_sum(a0); a1 = warp_sum(a1); a2 = warp_sum(a2); a3 = warp_sum(a3);
    if(lane==0){ red[0][wid]=a0; red[1][wid]=a1; red[2][wid]=a2; red[3][wid]=a3; }
    __syncthreads();
    if(tid < 4){
        float s = 0.f;
#pragma unroll
        for(int w=0; w<8; w++) s += red[tid][w];
        if(tid==3) s += film_b[j];
        g_v[tid*1024 + j] = s;
    }
}

// ================= fused prep =================
__device__ __forceinline__ void do_transpose(const float* __restrict__ src,
                                             __half* __restrict__ dst,
                                             int R, int C, int bx, int by,
                                             float tile[32][33]){
    int c0 = bx*32, r0 = by*32;
    int tx = threadIdx.x, ty = threadIdx.y;
#pragma unroll
    for(int i=0;i<32;i+=8)
        tile[ty+i][tx] = src[(size_t)(r0+ty+i)*C + c0+tx];
    __syncthreads();
#pragma unroll
    for(int i=0;i<32;i+=8)
        dst[(size_t)(c0+ty+i)*R + r0+tx] = __float2half_rn(tile[tx][ty+i]);
}

// blocks: [0,512) film-head; [512,1024) attn; [1024,2048) proj; [2048,10240) h; [10240,10752) wc
__global__ void k_prep(const float* __restrict__ film_w,
                       const float* __restrict__ attn_w1,
                       const float* __restrict__ proj_w1,
                       const float* __restrict__ h,
                       const float* __restrict__ w2q, const float* __restrict__ b2q,
                       const float* __restrict__ w2r, const float* __restrict__ b2r,
                       const float* __restrict__ w2b, const float* __restrict__ b2b,
                       const float* __restrict__ w2k, const float* __restrict__ b2k){
    __shared__ float tile[32][33];
    int b = blockIdx.x;
    if(b < 512){
        int bx = b&31, by = b>>5;
        int c0 = bx*32, r0 = by*32;
        int tx = threadIdx.x, ty = threadIdx.y;
#pragma unroll
        for(int i=0;i<32;i+=8)
            tile[ty+i][tx] = film_w[(size_t)(r0+ty+i)*1024 + c0+tx];
        __syncthreads();
#pragma unroll
        for(int i=0;i<32;i+=8){
            int c = c0+ty+i;
            int ic = (c<512) ? 2*c : 2*(c-512)+1;
            g_wt_film[(size_t)ic*DD + r0+tx] = __float2half_rn(tile[tx][ty+i]);
        }
    } else if(b < 1024){
        int bb = b - 512;
        int k  = bb >> 7; bb &= 127;
        do_transpose(attn_w1 + (size_t)k*DD*256, g_wt_attn + (size_t)k*256*DD,
                     DD, 256, bb&7, bb>>3, tile);
    } else if(b < 2048){
        int bb = b - 1024;
        int k  = bb >> 8; bb &= 255;
        do_transpose(proj_w1 + (size_t)k*DD*DD, g_wt_proj + (size_t)k*DD*DD,
                     DD, 512, bb&15, bb>>4, tile);
    } else if(b < 10240){
        int bb = b - 2048;
        int tid = threadIdx.y*32 + threadIdx.x;
        size_t i = (size_t)bb*1024 + tid*4;
        float4 v = *(const float4*)(h + i);
        __half2 h0 = __floats2half2_rn(v.x, v.y);
        __half2 h1 = __floats2half2_rn(v.z, v.w);
        *(__half2*)(g_ht + i)     = h0;
        *(__half2*)(g_ht + i + 2) = h1;
    } else {
        int c = b - 10240;
        int k = c >> 7, r = c & 127;
        int tid = threadIdx.y*32 + threadIdx.x;
        int vocab; const float *W, *bs2;
        if(k==0)      { vocab=64; W=w2q; bs2=b2q; }
        else if(k==1) { vocab=13; W=w2r; bs2=b2r; }
        else if(k==2) { vocab=13; W=w2b; bs2=b2b; }
        else          { vocab=25; W=w2k; bs2=b2k; }
        for(int d=tid; d<DD; d+=256){
            float val = (r < vocab) ? W[(size_t)d*vocab + r] : 0.f;
            g_wc[((size_t)k*128 + r)*DD + d] = __float2half_rn(val);
        }
        if(tid == 0) g_bc[k*128 + r] = (r < vocab) ? bs2[r] : 0.f;
    }
}

// ================= stage 1: bl = h . w_bnd + b =================
__global__ void k_bl(const float* __restrict__ h, const float* __restrict__ w,
                     const float* __restrict__ b0, float* __restrict__ out){
    int t    = blockIdx.x*8 + (threadIdx.x>>5);
    int lane = threadIdx.x&31;
    const float4* hr = (const float4*)(h + (size_t)t*DD);
    const float4* w4 = (const float4*)w;
    float acc = 0.f;
#pragma unroll
    for(int i=0;i<4;i++){
        float4 a = hr[lane + i*32];
        float4 b = w4[lane + i*32];
        acc += a.x*b.x + a.y*b.y + a.z*b.z + a.w*b.w;
    }
    acc = warp_sum(acc);
    if(lane==0){
        float v = acc + b0[0];
        g_bl[t] = v;
        out[(size_t)t*NCOL + 115] = v;
    }
}

// ================= stage 2: conv + sigmoid =================
__global__ void k_bsoft(const float* __restrict__ ck, const float* __restrict__ cb){
    int t  = blockIdx.x*256 + threadIdx.x;
    int b  = t / TT, tt = t - b*TT;
    float acc = cb[0];
#pragma unroll
    for(int j=0;j<9;j++){
        int tj = tt + j - 4;
        if(tj>=0 && tj<TT) acc = fmaf(g_bl[b*TT+tj], ck[j], acc);
    }
    g_bsoft[t] = 1.f/(1.f + expf(-acc));
}

// ================= stage 3: stats + hg + nh (+ sz init) =================
__global__ void k_filmin(const float* __restrict__ h, const float* __restrict__ e0,
                         const float* __restrict__ e1, const float* __restrict__ g,
                         const float* __restrict__ lng, const float* __restrict__ lnb,
                         const float* __restrict__ b2a){
    __shared__ float rbuf[4][8];
    int t = blockIdx.x;
    int lane = threadIdx.x&31, wid = threadIdx.x>>5;
    float bs = g_bsoft[t];
    const float* hr = h + (size_t)t*DD;
    float v[3];
#pragma unroll
    for(int c=0;c<3;c++){
        int i = threadIdx.x + c*256;
        float val = 0.f;
        if(i < DIN) val = (i < DD) ? hr[i] : (bs*e1[i-DD] + (1.f-bs)*e0[i-DD]);
        v[c] = val;
    }
    float s4[4];
    s4[0] = v[0]+v[1]+v[2];
    s4[1] = v[0]*v[0]+v[1]*v[1]+v[2]*v[2];
    s4[2] = v[0]+v[1];
    s4[3] = v[0]*v[0]+v[1]*v[1];
#pragma unroll
    for(int q=0;q<4;q++){
        s4[q] = warp_sum(s4[q]);
        if(lane==0) rbuf[q][wid] = s4[q];
    }
    __syncthreads();
    if(wid==0){
#pragma unroll
        for(int q=0;q<4;q++){
            float s = (lane<8)? rbuf[q][lane] : 0.f;
            s = warp_sum(s);
            if(lane==0) rbuf[q][0] = s;
        }
    }
    __syncthreads();
    float mu  = rbuf[0][0] / (float)DIN;
    float var = rbuf[1][0] / (float)DIN - mu*mu;
    float rstd = rsqrtf(var + 1e-5f);
    float muh  = rbuf[2][0] / (float)DD;
    float varh = rbuf[3][0] / (float)DD - muh*muh;
    float rstdh = rsqrtf(varh + 1e-5f);
    if(threadIdx.x == 0) g_st[t] = make_float4(bs, mu, rstd, 0.f);
    if(threadIdx.x < 4)  g_sz[(size_t)threadIdx.x*MM + t] = b2a[threadIdx.x];
#pragma unroll
    for(int c=0;c<2;c++){
        int i = threadIdx.x + c*256;
        g_filmin[(size_t)t*DD + i] = __float2half_rn(v[c]*g[i]);           // hg
        g_nh[(size_t)t*DD + i]     = __float2half_rn((v[c]-muh)*rstdh*lng[i] + lnb[i]);
    }
}

// ================= stage 8: softmax + pool (half of M via t0) =================
__global__ void k_pool(int t0){
    __shared__ float sa[4][10];
    __shared__ int   sidx[9];
    int t = blockIdx.x + t0;
    int b = t/TT, tt = t - b*TT;
    int tid = threadIdx.x;
    if(tid < 9){
        int tj = tt + tid - 4;
        tj = min(max(tj, 0), TT-1);
        sidx[tid] = b*TT + tj;
    }
    __syncthreads();
    if(tid < 4){
        int k = tid;
        float sc[10];
        sc[0] = g_sz[(size_t)k*MM + t];
#pragma unroll
        for(int j=0;j<9;j++) sc[1+j] = g_sh[(size_t)k*MM + sidx[j]];
        float mx = sc[0];
#pragma unroll
        for(int c=1;c<10;c++) mx = fmaxf(mx, sc[c]);
        float sum = 0.f;
#pragma unroll
        for(int c=0;c<10;c++){ sc[c] = expf(sc[c]-mx); sum += sc[c]; }
        float inv = 1.f/sum;
#pragma unroll
        for(int c=0;c<10;c++) sa[k][c] = sc[c]*inv;
    }
    __syncthreads();
    int d = tid*4;
    const __half2* zp = (const __half2*)(g_z + (size_t)t*DD + d);
    float2 zlo = __half22float2(zp[0]);
    float2 zhi = __half22float2(zp[1]);
    float4 zv = make_float4(zlo.x, zlo.y, zhi.x, zhi.y);
    float4 hv[9];
#pragma unroll
    for(int j=0;j<9;j++){
        const __half2* hp = (const __half2*)(g_ht + (size_t)sidx[j]*DD + d);
        float2 lo = __half22float2(hp[0]);
        float2 hi = __half22float2(hp[1]);
        hv[j] = make_float4(lo.x, lo.y, hi.x, hi.y);
    }
#pragma unroll
    for(int k=0;k<4;k++){
        float4 p;
        p.x = sa[k][0]*zv.x; p.y = sa[k][0]*zv.y;
        p.z = sa[k][0]*zv.z; p.w = sa[k][0]*zv.w;
#pragma unroll
        for(int j=0;j<9;j++){
            float w = sa[k][1+j];
            p.x = fmaf(w, hv[j].x, p.x); p.y = fmaf(w, hv[j].y, p.y);
            p.z = fmaf(w, hv[j].z, p.z); p.w = fmaf(w, hv[j].w, p.w);
        }
        __half2 o0 = __floats2half2_rn(p.x, p.y);
        __half2 o1 = __floats2half2_rn(p.z, p.w);
        __half2* op = (__half2*)(g_pool + ((size_t)k*MM + t)*DD + d);
        op[0] = o0; op[1] = o1;
    }
}

// ================= launch =================
extern "C" void kernel_launch(void* const* d_in, const int* in_sizes, int n_in,
                              void* d_out, int out_size){
    const float* h       = (const float*)d_in[0];
    const float* w_bnd   = (const float*)d_in[1];
    const float* b_bnd   = (const float*)d_in[2];
    const float* conv_k  = (const float*)d_in[3];
    const float* conv_b  = (const float*)d_in[4];
    const float* e0      = (const float*)d_in[5];
    const float* e1      = (const float*)d_in[6];
    const float* ln_in_g = (const float*)d_in[7];
    const float* ln_in_b = (const float*)d_in[8];
    const float* ln_h_g  = (const float*)d_in[9];
    const float* ln_h_b  = (const float*)d_in[10];
    const float* film_w  = (const float*)d_in[11];
    const float* film_b  = (const float*)d_in[12];
    const float* attn_w1 = (const float*)d_in[13];
    const float* attn_b1 = (const float*)d_in[14];
    const float* attn_w2 = (const float*)d_in[15];
    const float* attn_b2 = (const float*)d_in[16];
    const float* proj_w1 = (const float*)d_in[17];
    const float* proj_b1 = (const float*)d_in[18];
    const float* w2q = (const float*)d_in[19]; const float* b2q = (const float*)d_in[20];
    const float* w2r = (const float*)d_in[21]; const float* b2r = (const float*)d_in[22];
    const float* w2b = (const float*)d_in[23]; const float* b2b = (const float*)d_in[24];
    const float* w2k = (const float*)d_in[25]; const float* b2k = (const float*)d_in[26];
    float* out = (float*)d_out;

    __half *p_filmin, *p_nh, *p_z, *p_ht, *p_pool, *p_p1, *p_wtf, *p_wta, *p_wtp, *p_wc;
    float  *p_sh, *p_sz, *p_bc, *p_v, *p_st;
    cudaGetSymbolAddress((void**)&p_filmin, g_filmin);
    cudaGetSymbolAddress((void**)&p_nh,     g_nh);
    cudaGetSymbolAddress((void**)&p_z,      g_z);
    cudaGetSymbolAddress((void**)&p_ht,     g_ht);
    cudaGetSymbolAddress((void**)&p_sh,     g_sh);
    cudaGetSymbolAddress((void**)&p_sz,     g_sz);
    cudaGetSymbolAddress((void**)&p_pool,   g_pool);
    cudaGetSymbolAddress((void**)&p_p1,     g_p1);
    cudaGetSymbolAddress((void**)&p_wtf,    g_wt_film);
    cudaGetSymbolAddress((void**)&p_wta,    g_wt_attn);
    cudaGetSymbolAddress((void**)&p_wtp,    g_wt_proj);
    cudaGetSymbolAddress((void**)&p_wc,     g_wc);
    cudaGetSymbolAddress((void**)&p_bc,     g_bc);
    cudaGetSymbolAddress((void**)&p_v,      g_v);
    cudaGetSymbolAddress((void**)&p_st,     g_st);

    cudaFuncSetAttribute(tgemm, cudaFuncAttributeMaxDynamicSharedMemorySize, TG_SMEM);

    cudaStream_t s2 = g_ss.s2;
    const int HM = MM/2;   // 8192 = batch boundary

    // ---- fork side stream ----
    cudaEventRecord(g_ss.evF, 0);
    cudaStreamWaitEvent(s2, g_ss.evF, 0);

    // s2: prep + sh init
    k_prep<<<10752, dim3(32,8), 0, s2>>>(film_w, attn_w1, proj_w1, h,
                                         w2q, b2q, w2r, b2r, w2b, b2b, w2k, b2k);
    k_sinit<<<4*MM/256, 256, 0, s2>>>(p_sh, attn_b2);
    cudaEventRecord(g_ss.evP, s2);

    // main: gemv, bl, bsoft, filmin
    k_gemv<<<1024, 256>>>(film_w, e0, e1, ln_in_g, ln_in_b, film_b);
    k_bl<<<MM/8, 256>>>(h, w_bnd, b_bnd, out);
    k_bsoft<<<MM/256, 256>>>(conv_k, conv_b);
    k_filmin<<<MM, 256>>>(h, e0, e1, ln_in_g, ln_h_g, ln_h_b, attn_b2);
    cudaEventRecord(g_ss.evM, 0);

    // s2: hW1 full + fused score
    tgemm<<<dim3(8, MM/128, 1), 256, TG_SMEM, s2>>>(
        DD, p_ht, DD, p_wta, DD, p_sh, MM, attn_b1, 2,
        attn_w2, attn_b2, 0,0,0,0, 0);
    cudaEventRecord(g_ss.evH, s2);

    // s2 chain: half 1 (rows [8192,16384))
    cudaStreamWaitEvent(s2, g_ss.evM, 0);
    tgemm<<<dim3(8, HM/128, 1), 256, TG_SMEM, s2>>>(
        DD, p_filmin, DD, p_wtf, DD, (float*)p_z, DD, p_st, 3,
        (const float*)p_nh, p_v, 0,0,0,0, HM);
    tgemm<<<dim3(8, HM/128, 1), 256, TG_SMEM, s2>>>(
        DD, p_z, DD, p_wta, DD, p_sz, MM, attn_b1, 2,
        attn_w2, attn_b2, 0,0,0,0, HM);
    k_pool<<<HM, 128, 0, s2>>>(HM);
    tgemm<<<dim3(4, HM/128, 4), 256, TG_SMEM, s2>>>(
        DD, p_pool, DD, p_wtp, DD, (float*)p_p1, 2048, proj_b1, 1,
        nullptr, nullptr,
        (long long)MM*DD, (long long)DD*DD, 512LL, DD, HM);
    tgemm<<<dim3(1, HM/128, 4), 256, TG_SMEM, s2>>>(
        DD, p_p1, 2048, p_wc, DD, out, NCOL, p_bc, 4,
        nullptr, nullptr, 512LL, (long long)128*DD, 0, 128, HM);
    cudaEventRecord(g_ss.evJ, s2);

    // main chain: half 0 (rows [0,8192))
    cudaStreamWaitEvent(0, g_ss.evP, 0);
    tgemm<<<dim3(8, HM/128, 1), 256, TG_SMEM>>>(
        DD, p_filmin, DD, p_wtf, DD, (float*)p_z, DD, p_st, 3,
        (const float*)p_nh, p_v, 0,0,0,0, 0);
    tgemm<<<dim3(8, HM/128, 1), 256, TG_SMEM>>>(
        DD, p_z, DD, p_wta, DD, p_sz, MM, attn_b1, 2,
        attn_w2, attn_b2, 0,0,0,0, 0);
    cudaStreamWaitEvent(0, g_ss.evH, 0);
    k_pool<<<HM, 128>>>(0);
    tgemm<<<dim3(4, HM/128, 4), 256, TG_SMEM>>>(
        DD, p_pool, DD, p_wtp, DD, (float*)p_p1, 2048, proj_b1, 1,
        nullptr, nullptr,
        (long long)MM*DD, (long long)DD*DD, 512LL, DD, 0);
    tgemm<<<dim3(1, HM/128, 4), 256, TG_SMEM>>>(
        DD, p_p1, 2048, p_wc, DD, out, NCOL, p_bc, 4,
        nullptr, nullptr, 512LL, (long long)128*DD, 0, 128, 0);

    // join
    cudaStreamWaitEvent(0, g_ss.evJ, 0);
}